// round 14
// baseline (speedup 1.0000x reference)
#include <cuda_runtime.h>
#include <cuda_bf16.h>
#include <cstdint>

// Linear attention, fp32 I/O: out = (phi(Q) @ (phi(K)^T V)) / (phi(Q).Z + eps)
// B=2 H=32 q=2048 kv=8192 d=128.
// Fast path (sm_100a cubin): tcgen05 tf32 hi/lo Dekker split, fp32 TMEM acc.
//   kv_kernel: single-buffer TK=32 SW128 stage + asm-volatile REGISTER prefetch
//   of the next chunk; SPL=8 -> 512 CTAs to actually FILL 3 CTA/SM residency.
// Fallback (plain compute_100 PTX pass): FFMA register-tile GEMMs.

#define BH      64
#define QLEN    2048
#define KVLEN   8192
#define D       128
#define EPS     1e-6f

#define SPL     8                  // kv splits
#define KVCHUNK (KVLEN / SPL)      // 1024 rows per block
#define TK      32                 // kv tile depth per smem chunk (tf32)
#define NCHUNK  (KVCHUNK / TK)     // 32

#define QT      128                // q rows per out block
#define DK      32                 // d chunk in out kernel
#define NDCH    (D / DK)           // 4

#define TF32_MASK 0xFFFFE000u

// idesc: dtype F32, atype/btype TF32(2), N=128, M=128 ; K=8 per step
#define IDESC_TF32 ((1u<<4) | (2u<<7) | (2u<<10) | ((128u/8u)<<17) | ((128u/16u)<<24))

#if defined(__CUDA_ARCH_FEAT_SM100_ALL) || defined(__CUDA_ARCH_FEAT_SM101_ALL) || defined(__CUDA_ARCH_FEAT_SM103_ALL)
#define HAS_TCGEN05 1
#else
#define HAS_TCGEN05 0
#endif

__device__ float g_part[SPL * BH * D * D];   // per-split KVT partials, 32 MB
__device__ float g_Zpart[SPL * BH * D];
__device__ float g_KVThi[BH * D * D];        // tf32-masked hi, 4 MB
__device__ float g_KVTlo[BH * D * D];        // tf32-masked lo, 4 MB
__device__ float g_Z[BH * D];

// ---------------------------------------------------------------------------
// PTX helpers
// ---------------------------------------------------------------------------
__device__ __forceinline__ uint32_t smem_u32(const void* p) {
    uint32_t a;
    asm("{ .reg .u64 t; cvta.to.shared.u64 t, %1; cvt.u32.u64 %0, t; }" : "=r"(a) : "l"(p));
    return a;
}
__device__ __forceinline__ uint32_t elect_one() {
    uint32_t pred;
    asm volatile("{\n\t.reg .pred p;\n\telect.sync _|p, 0xFFFFFFFF;\n\tselp.b32 %0, 1, 0, p;\n\t}"
                 : "=r"(pred));
    return pred;
}

#if HAS_TCGEN05
#define TCGEN05_ALLOC(sa, n) \
    asm volatile("tcgen05.alloc.cta_group::1.sync.aligned.shared::cta.b32 [%0], %1;" \
                 :: "r"((uint32_t)(sa)), "r"((uint32_t)(n)) : "memory")
#define TCGEN05_DEALLOC(t, n) \
    asm volatile("tcgen05.dealloc.cta_group::1.sync.aligned.b32 %0, %1;" :: "r"(t), "r"((uint32_t)(n)))
#define TCGEN05_RELINQ() \
    asm volatile("tcgen05.relinquish_alloc_permit.cta_group::1.sync.aligned;")
#define TCGEN05_COMMIT(mb) \
    asm volatile("tcgen05.commit.cta_group::1.mbarrier::arrive::one.shared::cluster.b64 [%0];" \
                 :: "r"((uint32_t)(mb)) : "memory")
#define TCGEN05_FENCE_AFTER()  asm volatile("tcgen05.fence::after_thread_sync;" ::: "memory")
#define TCGEN05_WAIT_LD()      asm volatile("tcgen05.wait::ld.sync.aligned;" ::: "memory")
#define FENCE_ASYNC_SHARED()   asm volatile("fence.proxy.async.shared::cta;" ::: "memory")

#define MBARRIER_INIT(mb, cnt) \
    asm volatile("mbarrier.init.shared.b64 [%0], %1;" :: "r"((uint32_t)(mb)), "r"((uint32_t)(cnt)) : "memory")
#define MBARRIER_INVAL(mb) \
    asm volatile("mbarrier.inval.shared.b64 [%0];" :: "r"((uint32_t)(mb)) : "memory")

__device__ __forceinline__ void mbar_wait(uint32_t mb, uint32_t parity) {
    uint32_t done;
    asm volatile("{\n\t.reg .pred p;\n\t"
                 "mbarrier.try_wait.parity.acquire.cta.shared::cta.b64 p, [%1], %2;\n\t"
                 "selp.b32 %0, 1, 0, p;\n\t}" : "=r"(done) : "r"(mb), "r"(parity) : "memory");
    if (!done) {
        asm volatile("{\n\t.reg .pred P1;\n\t"
                     "WL_%=:\n\t"
                     "mbarrier.try_wait.parity.acquire.cta.shared::cta.b64 P1, [%0], %1, 0x989680;\n\t"
                     "@P1 bra.uni WD_%=;\n\t"
                     "bra.uni WL_%=;\n\t"
                     "WD_%=:\n\t}" :: "r"(mb), "r"(parity) : "memory");
    }
}

__device__ __forceinline__ void mma_tf32_ss(uint32_t d_tmem, uint64_t a_desc, uint64_t b_desc,
                                            bool acc) {
    uint32_t en = acc ? 1u : 0u;
    asm volatile("{\n\t.reg .pred p;\n\tsetp.ne.u32 p, %5, 0;\n\t"
                 "tcgen05.mma.cta_group::1.kind::tf32 [%0], %1, %2, %3, {%4, %4, %4, %4}, p;\n\t}"
                 :: "r"(d_tmem), "l"(a_desc), "l"(b_desc), "r"((uint32_t)IDESC_TF32), "r"(0u), "r"(en)
                 : "memory");
}

#define LDTM_X32(r, ta) \
    asm volatile("tcgen05.ld.sync.aligned.32x32b.x32.b32 " \
        "{%0,%1,%2,%3,%4,%5,%6,%7,%8,%9,%10,%11,%12,%13,%14,%15," \
        "%16,%17,%18,%19,%20,%21,%22,%23,%24,%25,%26,%27,%28,%29,%30,%31}, [%32];" \
        : "=r"((r)[0]),"=r"((r)[1]),"=r"((r)[2]),"=r"((r)[3]),"=r"((r)[4]),"=r"((r)[5]),"=r"((r)[6]),"=r"((r)[7]), \
          "=r"((r)[8]),"=r"((r)[9]),"=r"((r)[10]),"=r"((r)[11]),"=r"((r)[12]),"=r"((r)[13]),"=r"((r)[14]),"=r"((r)[15]), \
          "=r"((r)[16]),"=r"((r)[17]),"=r"((r)[18]),"=r"((r)[19]),"=r"((r)[20]),"=r"((r)[21]),"=r"((r)[22]),"=r"((r)[23]), \
          "=r"((r)[24]),"=r"((r)[25]),"=r"((r)[26]),"=r"((r)[27]),"=r"((r)[28]),"=r"((r)[29]),"=r"((r)[30]),"=r"((r)[31]) \
        : "r"(ta))
#endif // HAS_TCGEN05

#define STS128(a, r0, r1, r2, r3) \
    asm volatile("st.shared.v4.b32 [%0], {%1, %2, %3, %4};" :: "r"(a), "r"(r0), "r"(r1), "r"(r2), "r"(r3) : "memory")

// Volatile global load — pinned in program order, ptxas cannot sink it.
#define LDGV(dst, p, IMM) \
    asm volatile("ld.global.nc.f32 %0, [%1+" #IMM "];" : "=f"(dst) : "l"(p))
// 16 column-strided loads (stride D*4 = 512B)
#define PREFETCH16(dst, base) do { \
    LDGV((dst)[0],  (base), 0);    LDGV((dst)[1],  (base), 512);  \
    LDGV((dst)[2],  (base), 1024); LDGV((dst)[3],  (base), 1536); \
    LDGV((dst)[4],  (base), 2048); LDGV((dst)[5],  (base), 2560); \
    LDGV((dst)[6],  (base), 3072); LDGV((dst)[7],  (base), 3584); \
    LDGV((dst)[8],  (base), 4096); LDGV((dst)[9],  (base), 4608); \
    LDGV((dst)[10], (base), 5120); LDGV((dst)[11], (base), 5632); \
    LDGV((dst)[12], (base), 6144); LDGV((dst)[13], (base), 6656); \
    LDGV((dst)[14], (base), 7168); LDGV((dst)[15], (base), 7680); \
} while (0)

// SMEM descriptor: SW128, version 1 (Blackwell), SBO=64, LBO=1
#define SMEM_DESC_BASE ((uint64_t(2)<<61) | (uint64_t(1)<<46) | (uint64_t(64)<<32) | (uint64_t(1)<<16))
#define MAKE_DESC(addr) (SMEM_DESC_BASE | ((uint64_t)((addr) >> 4) & 0x3FFF))
#define SWZ(b) ((b) ^ (((b) >> 3) & 0x70))

// byte offset for K-major tiles: 128 rows x 32 tf32 (128B rows)
__device__ __forceinline__ uint32_t koff(int row, int col) {
    uint32_t b = (uint32_t)row * 128u + (uint32_t)col * 4u;
    return SWZ(b);
}

__device__ __forceinline__ float phi(float x) { return x > 0.f ? x + 1.f : __expf(x); }

// Dekker truncation split: x = hi + lo with hi, lo tf32-representable.
__device__ __forceinline__ void split_tf32(float x, float& h, float& l) {
    h = __uint_as_float(__float_as_uint(x) & TF32_MASK);
    float lf = x - h;                 // exact
    l = __uint_as_float(__float_as_uint(lf) & TF32_MASK);
}

// ---------------------------------------------------------------------------
// kv_kernel: part[split][bh][e][d] = sum_kv V[kv][e]*phi(K[kv][d]); Zpart likewise
// Single-buffer smem stage; asm-volatile register prefetch; 3 CTA/SM, 512 CTAs.
// ---------------------------------------------------------------------------
__global__ __launch_bounds__(256, 3) void kv_kernel(const float* __restrict__ K,
                                                    const float* __restrict__ V) {
    extern __shared__ char dyns[];
    const int tid = threadIdx.x;
    const int bh = blockIdx.x / SPL;
    const int split = blockIdx.x % SPL;
    const float* Kp = K + ((size_t)bh * KVLEN + (size_t)split * KVCHUNK) * D;
    const float* Vp = V + ((size_t)bh * KVLEN + (size_t)split * KVCHUNK) * D;

#if HAS_TCGEN05
    __shared__ uint32_t s_tmem;
    __shared__ __align__(8) unsigned long long s_mbar;
    __shared__ float sZ[D];
    const int wid = tid >> 5;

    uint32_t sbase = (smem_u32(dyns) + 1023u) & ~1023u;
    const uint32_t AH = sbase;             // V hi    [128 e][32 kv] tf32
    const uint32_t AL = sbase + 16384;     // V lo
    const uint32_t BHt = sbase + 32768;    // phiK hi [128 d][32 kv]
    const uint32_t BLt = sbase + 49152;    // phiK lo
    uint32_t mbar = smem_u32(&s_mbar);

    if (wid == 0) {
        TCGEN05_ALLOC(smem_u32(&s_tmem), 128);
        TCGEN05_RELINQ();
    }
    if (tid == 0) MBARRIER_INIT(mbar, 1);
    if (tid < D) sZ[tid] = 0.f;
    __syncthreads();
    const uint32_t tmem = s_tmem;

    const int lane_c = tid & 127;          // column: e for V, d for K
    const int g = tid >> 7;                // row half: rows g*16 .. g*16+15
    float zacc = 0.f;

    const uint64_t adesc = MAKE_DESC(AH), aldesc = MAKE_DESC(AL);
    const uint64_t bdesc = MAKE_DESC(BHt), bldesc = MAKE_DESC(BLt);

    float vV[16], vK[16];                  // prefetched RAW operands

    // prologue: volatile prefetch of chunk 0
    PREFETCH16(vV, Vp + (size_t)(g * 16) * D + lane_c);
    PREFETCH16(vK, Kp + (size_t)(g * 16) * D + lane_c);

    for (int chunk = 0; chunk < NCHUNK; chunk++) {
        // wait until MMAs of chunk-1 finished reading the stage
        if (chunk > 0) mbar_wait(mbar, (uint32_t)((chunk - 1) & 1));
        __syncthreads();

        // consume prefetched registers: phi (K side), split, STS
#pragma unroll
        for (int j = 0; j < 4; j++) {
            float h0, l0, h1, l1, h2, l2, h3, l3;
            split_tf32(vV[j*4+0], h0, l0);
            split_tf32(vV[j*4+1], h1, l1);
            split_tf32(vV[j*4+2], h2, l2);
            split_tf32(vV[j*4+3], h3, l3);
            uint32_t off = koff(lane_c, g * 16 + j * 4);
            STS128(AH + off, __float_as_uint(h0), __float_as_uint(h1),
                             __float_as_uint(h2), __float_as_uint(h3));
            STS128(AL + off, __float_as_uint(l0), __float_as_uint(l1),
                             __float_as_uint(l2), __float_as_uint(l3));
        }
#pragma unroll
        for (int j = 0; j < 4; j++) {
            float p0 = phi(vK[j*4+0]), p1 = phi(vK[j*4+1]);
            float p2 = phi(vK[j*4+2]), p3 = phi(vK[j*4+3]);
            zacc += p0 + p1 + p2 + p3;
            float h0, l0, h1, l1, h2, l2, h3, l3;
            split_tf32(p0, h0, l0); split_tf32(p1, h1, l1);
            split_tf32(p2, h2, l2); split_tf32(p3, h3, l3);
            uint32_t off = koff(lane_c, g * 16 + j * 4);
            STS128(BHt + off, __float_as_uint(h0), __float_as_uint(h1),
                              __float_as_uint(h2), __float_as_uint(h3));
            STS128(BLt + off, __float_as_uint(l0), __float_as_uint(l1),
                              __float_as_uint(l2), __float_as_uint(l3));
        }
        __syncthreads();
        FENCE_ASYNC_SHARED();

        if (wid == 0 && elect_one()) {
#pragma unroll
            for (int ks = 0; ks < 4; ks++) {          // 32 kv = 4 K8-steps
                uint64_t o = (uint64_t)(ks * 2);
                mma_tf32_ss(tmem, adesc + o, bdesc + o, !(chunk == 0 && ks == 0));
                mma_tf32_ss(tmem, adesc + o, bldesc + o, true);
                mma_tf32_ss(tmem, aldesc + o, bdesc + o, true);
            }
            TCGEN05_COMMIT(mbar);
        }

        // volatile prefetch of chunk+1 — flies during the MMA wait
        if (chunk + 1 < NCHUNK) {
            const int k0 = (chunk + 1) * TK + g * 16;
            PREFETCH16(vV, Vp + (size_t)k0 * D + lane_c);
            PREFETCH16(vK, Kp + (size_t)k0 * D + lane_c);
        }
    }

    atomicAdd(&sZ[lane_c], zacc);
    mbar_wait(mbar, (uint32_t)((NCHUNK - 1) & 1));
    TCGEN05_FENCE_AFTER();

    {   // epilogue: plain stores to this split's partial buffer
        const int sub = wid & 3;
        const int colbase = (wid >> 2) * 64;
        const int row = sub * 32 + (tid & 31);       // e
        float* dst = g_part + ((size_t)split * BH + bh) * D * D + (size_t)row * D;
#pragma unroll
        for (int cb = 0; cb < 64; cb += 32) {
            uint32_t r[32];
            LDTM_X32(r, tmem + colbase + cb);
            TCGEN05_WAIT_LD();
#pragma unroll
            for (int j4 = 0; j4 < 8; j4++) {
                float4 o;
                o.x = __uint_as_float(r[j4*4+0]);
                o.y = __uint_as_float(r[j4*4+1]);
                o.z = __uint_as_float(r[j4*4+2]);
                o.w = __uint_as_float(r[j4*4+3]);
                *(float4*)(dst + colbase + cb + j4*4) = o;
            }
        }
    }
    __syncthreads();
    if (tid < D)
        g_Zpart[(size_t)split * BH * D + (size_t)bh * D + tid] = sZ[tid];

    if (tid == 0) MBARRIER_INVAL(mbar);
    __syncthreads();
    if (wid == 0) TCGEN05_DEALLOC(tmem, 128);

#else  // ------------------- FFMA fallback -------------------
    const int FKT = 16;
    float* As = (float*)dyns;                 // [FKT][D] phiK
    float* Bs = As + FKT * D;                 // [FKT][D] V

    const int tx = tid & 15;                  // e group
    const int ty = tid >> 4;                  // d group

    float acc[8][8];
#pragma unroll
    for (int i = 0; i < 8; i++)
#pragma unroll
        for (int j = 0; j < 8; j++) acc[i][j] = 0.f;
    float zacc = 0.f;

    for (int k0 = 0; k0 < KVCHUNK; k0 += FKT) {
#pragma unroll
        for (int r = 0; r < 2; r++) {
            int idx = tid + r * 256;
            int row = idx >> 5;
            int c4 = (idx & 31) * 4;
            float4 kq = *(const float4*)(Kp + (size_t)(k0 + row) * D + c4);
            As[row * D + c4 + 0] = phi(kq.x);
            As[row * D + c4 + 1] = phi(kq.y);
            As[row * D + c4 + 2] = phi(kq.z);
            As[row * D + c4 + 3] = phi(kq.w);
            float4 vq = *(const float4*)(Vp + (size_t)(k0 + row) * D + c4);
            Bs[row * D + c4 + 0] = vq.x;
            Bs[row * D + c4 + 1] = vq.y;
            Bs[row * D + c4 + 2] = vq.z;
            Bs[row * D + c4 + 3] = vq.w;
        }
        __syncthreads();
#pragma unroll
        for (int kk = 0; kk < FKT; kk++) {
            float a[8], b[8];
#pragma unroll
            for (int i = 0; i < 8; i++) a[i] = As[kk * D + ty + 16 * i];
#pragma unroll
            for (int j = 0; j < 8; j++) b[j] = Bs[kk * D + tx + 16 * j];
#pragma unroll
            for (int i = 0; i < 8; i++)
#pragma unroll
                for (int j = 0; j < 8; j++) acc[i][j] = fmaf(a[i], b[j], acc[i][j]);
        }
        if (tid < D) {
            float s = 0.f;
#pragma unroll
            for (int kk = 0; kk < FKT; kk++) s += As[kk * D + tid];
            zacc += s;
        }
        __syncthreads();
    }

    float* dst = g_part + ((size_t)split * BH + bh) * D * D;
#pragma unroll
    for (int i = 0; i < 8; i++) {
        int drow = ty + 16 * i;
#pragma unroll
        for (int j = 0; j < 8; j++) {
            int ecol = tx + 16 * j;
            dst[(size_t)ecol * D + drow] = acc[i][j];   // transposed store
        }
    }
    if (tid < D)
        g_Zpart[(size_t)split * BH * D + (size_t)bh * D + tid] = zacc;
#endif
}

// ---------------------------------------------------------------------------
// reduce_kernel: sum SPL partials -> KVT hi/lo (tf32-masked) + Z
// ---------------------------------------------------------------------------
__global__ __launch_bounds__(256) void reduce_kernel() {
    const int gid = blockIdx.x * blockDim.x + threadIdx.x;
    const int n4 = BH * D * D / 4;
    const size_t stride4 = (size_t)BH * D * D / 4;
    const float4* P = (const float4*)g_part;
    float4* Hi = (float4*)g_KVThi;
    float4* Lo = (float4*)g_KVTlo;

    for (int i = gid; i < n4; i += gridDim.x * blockDim.x) {
        float4 s = P[i];
#pragma unroll
        for (int sp = 1; sp < SPL; sp++) {
            float4 p = P[(size_t)sp * stride4 + i];
            s.x += p.x; s.y += p.y; s.z += p.z; s.w += p.w;
        }
        float4 h, l;
        split_tf32(s.x, h.x, l.x);
        split_tf32(s.y, h.y, l.y);
        split_tf32(s.z, h.z, l.z);
        split_tf32(s.w, h.w, l.w);
        Hi[i] = h; Lo[i] = l;
    }

    const int nz = BH * D;
    for (int i = gid; i < nz; i += gridDim.x * blockDim.x) {
        float s = 0.f;
#pragma unroll
        for (int sp = 0; sp < SPL; sp++) s += g_Zpart[(size_t)sp * nz + i];
        g_Z[i] = s;
    }
}

// ---------------------------------------------------------------------------
// out_kernel: D2[q][e] = sum_d phiQ[q][d]*KVT[e][d]; out = D2 / (phiQ.Z + eps)
// ---------------------------------------------------------------------------
__global__ __launch_bounds__(256, 3) void out_kernel(const float* __restrict__ Q,
                                                     float* __restrict__ out) {
    extern __shared__ char dyns[];
    __shared__ float Zs[D];
    __shared__ float sdenom[QT];

    const int tid = threadIdx.x;
    const int bh = blockIdx.y;
    const int q0 = blockIdx.x * QT;
    const float* Qp = Q + ((size_t)bh * QLEN + q0) * D;
    const float* KHp = g_KVThi + (size_t)bh * D * D;
    const float* KLp = g_KVTlo + (size_t)bh * D * D;
    float* outp = out + ((size_t)bh * QLEN + q0) * D;

    if (tid < D) Zs[tid] = g_Z[bh * D + tid];
    if (tid < QT) sdenom[tid] = 0.f;

#if HAS_TCGEN05
    __shared__ uint32_t s_tmem;
    __shared__ __align__(8) unsigned long long s_mbar;
    const int wid = tid >> 5;
    const int lane = tid & 31;

    uint32_t sbase = (smem_u32(dyns) + 1023u) & ~1023u;
    const uint32_t AH = sbase;              // phiQ hi [128 q][32 d]
    const uint32_t AL = sbase + 16384;
    const uint32_t BHt = sbase + 32768;     // KVT hi  [128 e][32 d]
    const uint32_t BLt = sbase + 49152;
    uint32_t mbar = smem_u32(&s_mbar);

    if (wid == 0) {
        TCGEN05_ALLOC(smem_u32(&s_tmem), 128);
        TCGEN05_RELINQ();
    }
    if (tid == 0) MBARRIER_INIT(mbar, 1);
    __syncthreads();
    const uint32_t tmem = s_tmem;

    const uint64_t ah = MAKE_DESC(AH), al = MAKE_DESC(AL);
    const uint64_t bb = MAKE_DESC(BHt), bl = MAKE_DESC(BLt);

    for (int it = 0; it < NDCH; it++) {
        if (it > 0) mbar_wait(mbar, (uint32_t)((it - 1) & 1));
        __syncthreads();

        const int d0 = it * DK;
        // phiQ tiles: 128 rows x 32 d = 1024 float4, 4 per thread (8 threads/row)
#pragma unroll
        for (int s = 0; s < 4; s++) {
            int idx = s * 256 + tid;
            int row = idx >> 3;
            int c4 = (idx & 7) * 4;
            float4 v = *(const float4*)(Qp + (size_t)row * D + d0 + c4);
            float p0 = phi(v.x), p1 = phi(v.y), p2 = phi(v.z), p3 = phi(v.w);
            // denominator partial for THIS row, reduced over its 8 lanes now
            float dpart = p0 * Zs[d0 + c4] + p1 * Zs[d0 + c4 + 1]
                        + p2 * Zs[d0 + c4 + 2] + p3 * Zs[d0 + c4 + 3];
            dpart += __shfl_xor_sync(0xFFFFFFFFu, dpart, 4);
            dpart += __shfl_xor_sync(0xFFFFFFFFu, dpart, 2);
            dpart += __shfl_xor_sync(0xFFFFFFFFu, dpart, 1);
            if ((lane & 7) == 0) atomicAdd(&sdenom[row], dpart);
            float h0, l0, h1, l1, h2, l2, h3, l3;
            split_tf32(p0, h0, l0); split_tf32(p1, h1, l1);
            split_tf32(p2, h2, l2); split_tf32(p3, h3, l3);
            uint32_t off = koff(row, c4);
            STS128(AH + off, __float_as_uint(h0), __float_as_uint(h1),
                             __float_as_uint(h2), __float_as_uint(h3));
            STS128(AL + off, __float_as_uint(l0), __float_as_uint(l1),
                             __float_as_uint(l2), __float_as_uint(l3));
        }
        // KVT tiles: pre-masked, pure copy
#pragma unroll
        for (int s = 0; s < 4; s++) {
            int idx = s * 256 + tid;
            int row = idx >> 3;
            int c4 = (idx & 7) * 4;
            uint32_t off = koff(row, c4);
            float4 h = *(const float4*)(KHp + (size_t)row * D + d0 + c4);
            STS128(BHt + off, __float_as_uint(h.x), __float_as_uint(h.y),
                              __float_as_uint(h.z), __float_as_uint(h.w));
            float4 l = *(const float4*)(KLp + (size_t)row * D + d0 + c4);
            STS128(BLt + off, __float_as_uint(l.x), __float_as_uint(l.y),
                              __float_as_uint(l.z), __float_as_uint(l.w));
        }
        __syncthreads();
        FENCE_ASYNC_SHARED();

        if (wid == 0 && elect_one()) {
#pragma unroll
            for (int ks = 0; ks < 4; ks++) {
                uint64_t o = (uint64_t)(ks * 2);
                mma_tf32_ss(tmem, ah + o, bb + o, !(it == 0 && ks == 0));
                mma_tf32_ss(tmem, ah + o, bl + o, true);
                mma_tf32_ss(tmem, al + o, bb + o, true);
            }
            TCGEN05_COMMIT(mbar);
        }
    }

    mbar_wait(mbar, (uint32_t)((NDCH - 1) & 1));
    TCGEN05_FENCE_AFTER();
    __syncthreads();

    // epilogue: TMEM -> smem bounce (stride 129, conflict-free) -> coalesced STG
    float* sb = (float*)((char*)dyns + (sbase - smem_u32(dyns)));
    if (tid < QT) {
        const int row = tid;
        const float rd = 1.f / (sdenom[row] + EPS);
#pragma unroll
        for (int cb = 0; cb < 128; cb += 32) {
            uint32_t r[32];
            LDTM_X32(r, tmem + cb);
            TCGEN05_WAIT_LD();
#pragma unroll
            for (int j = 0; j < 32; j++)
                sb[row * 129 + cb + j] = __uint_as_float(r[j]) * rd;
        }
    }
    __syncthreads();

#pragma unroll
    for (int it = 0; it < 16; it++) {
        int idx = it * 256 + tid;
        int row = idx >> 5;
        int c4 = (idx & 31) * 4;
        float4 o;
        o.x = sb[row * 129 + c4];
        o.y = sb[row * 129 + c4 + 1];
        o.z = sb[row * 129 + c4 + 2];
        o.w = sb[row * 129 + c4 + 3];
        *(float4*)(outp + (size_t)row * D + c4) = o;
    }

    __syncthreads();
    if (tid == 0) MBARRIER_INVAL(mbar);
    __syncthreads();
    if (wid == 0) TCGEN05_DEALLOC(tmem, 128);

#else  // ------------------- FFMA fallback -------------------
    const int FKT = 16;
    float* Qs = (float*)dyns;                 // [128][17] phiQ chunk
    float* Ks = Qs + 128 * 17;                // [128][17] KVT chunk

    const int tx = tid & 15;                  // e group
    const int ty = tid >> 4;                  // q group

    float acc[8][8];
#pragma unroll
    for (int i = 0; i < 8; i++)
#pragma unroll
        for (int j = 0; j < 8; j++) acc[i][j] = 0.f;
    float dsum = 0.f;
    __syncthreads();

    for (int k0 = 0; k0 < D; k0 += FKT) {
#pragma unroll
        for (int r = 0; r < 2; r++) {
            int idx = tid + r * 256;
            int row = idx >> 2;
            int c4 = (idx & 3) * 4;
            float4 qv = *(const float4*)(Qp + (size_t)row * D + k0 + c4);
            Qs[row * 17 + c4 + 0] = phi(qv.x);
            Qs[row * 17 + c4 + 1] = phi(qv.y);
            Qs[row * 17 + c4 + 2] = phi(qv.z);
            Qs[row * 17 + c4 + 3] = phi(qv.w);
            float4 kh = *(const float4*)(KHp + (size_t)row * D + k0 + c4);
            float4 kl = *(const float4*)(KLp + (size_t)row * D + k0 + c4);
            Ks[row * 17 + c4 + 0] = kh.x + kl.x;
            Ks[row * 17 + c4 + 1] = kh.y + kl.y;
            Ks[row * 17 + c4 + 2] = kh.z + kl.z;
            Ks[row * 17 + c4 + 3] = kh.w + kl.w;
        }
        __syncthreads();
#pragma unroll
        for (int kk = 0; kk < FKT; kk++) {
            float a[8], b[8];
#pragma unroll
            for (int i = 0; i < 8; i++) a[i] = Qs[(ty + 16 * i) * 17 + kk];
#pragma unroll
            for (int j = 0; j < 8; j++) b[j] = Ks[(tx + 16 * j) * 17 + kk];
#pragma unroll
            for (int i = 0; i < 8; i++)
#pragma unroll
                for (int j = 0; j < 8; j++) acc[i][j] = fmaf(a[i], b[j], acc[i][j]);
        }
        if (tid < QT) {
            float s = 0.f;
#pragma unroll
            for (int kk = 0; kk < FKT; kk++) s += Qs[tid * 17 + kk] * Zs[k0 + kk];
            dsum += s;
        }
        __syncthreads();
    }

    if (tid < QT) sdenom[tid] = 1.f / (dsum + EPS);
    __syncthreads();

#pragma unroll
    for (int i = 0; i < 8; i++) {
        int row = ty + 16 * i;
        float rd = sdenom[row];
#pragma unroll
        for (int j = 0; j < 8; j++)
            outp[(size_t)row * D + tx + 16 * j] = acc[i][j] * rd;
    }
#endif
}

extern "C" void kernel_launch(void* const* d_in, const int* in_sizes, int n_in,
                              void* d_out, int out_size) {
    const float* Q = (const float*)d_in[0];
    const float* K = (const float*)d_in[1];
    const float* V = (const float*)d_in[2];
    float* out = (float*)d_out;

    cudaFuncSetAttribute(kv_kernel, cudaFuncAttributeMaxDynamicSharedMemorySize, 66560);
    cudaFuncSetAttribute(out_kernel, cudaFuncAttributeMaxDynamicSharedMemorySize, 67584);

    kv_kernel<<<BH * SPL, 256, 66560>>>(K, V);
    reduce_kernel<<<512, 256>>>();
    out_kernel<<<dim3(QLEN / QT, BH), 256, 67584>>>(Q, out);
}

// round 15
// speedup vs baseline: 1.1802x; 1.1802x over previous
#include <cuda_runtime.h>
#include <cuda_bf16.h>
#include <cstdint>

// Linear attention, fp32 I/O: out = (phi(Q) @ (phi(K)^T V)) / (phi(Q).Z + eps)
// B=2 H=32 q=2048 kv=8192 d=128.
// Fast path (sm_100a cubin): tcgen05 tf32 hi/lo Dekker split, fp32 TMEM acc.
//   kv_kernel: R13 config (SPL=4, lb(256,3), asm-volatile register prefetch).
//   out_kernel: same prefetch trick applied to the Q d-chunk loads.
// Fallback (plain compute_100 PTX pass): FFMA register-tile GEMMs.

#define BH      64
#define QLEN    2048
#define KVLEN   8192
#define D       128
#define EPS     1e-6f

#define SPL     4                  // kv splits
#define KVCHUNK (KVLEN / SPL)      // 2048 rows per block
#define TK      32                 // kv tile depth per smem chunk (tf32)
#define NCHUNK  (KVCHUNK / TK)     // 64

#define QT      128                // q rows per out block
#define DK      32                 // d chunk in out kernel
#define NDCH    (D / DK)           // 4

#define TF32_MASK 0xFFFFE000u

// idesc: dtype F32, atype/btype TF32(2), N=128, M=128 ; K=8 per step
#define IDESC_TF32 ((1u<<4) | (2u<<7) | (2u<<10) | ((128u/8u)<<17) | ((128u/16u)<<24))

#if defined(__CUDA_ARCH_FEAT_SM100_ALL) || defined(__CUDA_ARCH_FEAT_SM101_ALL) || defined(__CUDA_ARCH_FEAT_SM103_ALL)
#define HAS_TCGEN05 1
#else
#define HAS_TCGEN05 0
#endif

__device__ float g_part[SPL * BH * D * D];   // per-split KVT partials, 16 MB
__device__ float g_Zpart[SPL * BH * D];
__device__ float g_KVThi[BH * D * D];        // tf32-masked hi, 4 MB
__device__ float g_KVTlo[BH * D * D];        // tf32-masked lo, 4 MB
__device__ float g_Z[BH * D];

// ---------------------------------------------------------------------------
// PTX helpers
// ---------------------------------------------------------------------------
__device__ __forceinline__ uint32_t smem_u32(const void* p) {
    uint32_t a;
    asm("{ .reg .u64 t; cvta.to.shared.u64 t, %1; cvt.u32.u64 %0, t; }" : "=r"(a) : "l"(p));
    return a;
}
__device__ __forceinline__ uint32_t elect_one() {
    uint32_t pred;
    asm volatile("{\n\t.reg .pred p;\n\telect.sync _|p, 0xFFFFFFFF;\n\tselp.b32 %0, 1, 0, p;\n\t}"
                 : "=r"(pred));
    return pred;
}

#if HAS_TCGEN05
#define TCGEN05_ALLOC(sa, n) \
    asm volatile("tcgen05.alloc.cta_group::1.sync.aligned.shared::cta.b32 [%0], %1;" \
                 :: "r"((uint32_t)(sa)), "r"((uint32_t)(n)) : "memory")
#define TCGEN05_DEALLOC(t, n) \
    asm volatile("tcgen05.dealloc.cta_group::1.sync.aligned.b32 %0, %1;" :: "r"(t), "r"((uint32_t)(n)))
#define TCGEN05_RELINQ() \
    asm volatile("tcgen05.relinquish_alloc_permit.cta_group::1.sync.aligned;")
#define TCGEN05_COMMIT(mb) \
    asm volatile("tcgen05.commit.cta_group::1.mbarrier::arrive::one.shared::cluster.b64 [%0];" \
                 :: "r"((uint32_t)(mb)) : "memory")
#define TCGEN05_FENCE_AFTER()  asm volatile("tcgen05.fence::after_thread_sync;" ::: "memory")
#define TCGEN05_WAIT_LD()      asm volatile("tcgen05.wait::ld.sync.aligned;" ::: "memory")
#define FENCE_ASYNC_SHARED()   asm volatile("fence.proxy.async.shared::cta;" ::: "memory")

#define MBARRIER_INIT(mb, cnt) \
    asm volatile("mbarrier.init.shared.b64 [%0], %1;" :: "r"((uint32_t)(mb)), "r"((uint32_t)(cnt)) : "memory")
#define MBARRIER_INVAL(mb) \
    asm volatile("mbarrier.inval.shared.b64 [%0];" :: "r"((uint32_t)(mb)) : "memory")

__device__ __forceinline__ void mbar_wait(uint32_t mb, uint32_t parity) {
    uint32_t done;
    asm volatile("{\n\t.reg .pred p;\n\t"
                 "mbarrier.try_wait.parity.acquire.cta.shared::cta.b64 p, [%1], %2;\n\t"
                 "selp.b32 %0, 1, 0, p;\n\t}" : "=r"(done) : "r"(mb), "r"(parity) : "memory");
    if (!done) {
        asm volatile("{\n\t.reg .pred P1;\n\t"
                     "WL_%=:\n\t"
                     "mbarrier.try_wait.parity.acquire.cta.shared::cta.b64 P1, [%0], %1, 0x989680;\n\t"
                     "@P1 bra.uni WD_%=;\n\t"
                     "bra.uni WL_%=;\n\t"
                     "WD_%=:\n\t}" :: "r"(mb), "r"(parity) : "memory");
    }
}

__device__ __forceinline__ void mma_tf32_ss(uint32_t d_tmem, uint64_t a_desc, uint64_t b_desc,
                                            bool acc) {
    uint32_t en = acc ? 1u : 0u;
    asm volatile("{\n\t.reg .pred p;\n\tsetp.ne.u32 p, %5, 0;\n\t"
                 "tcgen05.mma.cta_group::1.kind::tf32 [%0], %1, %2, %3, {%4, %4, %4, %4}, p;\n\t}"
                 :: "r"(d_tmem), "l"(a_desc), "l"(b_desc), "r"((uint32_t)IDESC_TF32), "r"(0u), "r"(en)
                 : "memory");
}

#define LDTM_X32(r, ta) \
    asm volatile("tcgen05.ld.sync.aligned.32x32b.x32.b32 " \
        "{%0,%1,%2,%3,%4,%5,%6,%7,%8,%9,%10,%11,%12,%13,%14,%15," \
        "%16,%17,%18,%19,%20,%21,%22,%23,%24,%25,%26,%27,%28,%29,%30,%31}, [%32];" \
        : "=r"((r)[0]),"=r"((r)[1]),"=r"((r)[2]),"=r"((r)[3]),"=r"((r)[4]),"=r"((r)[5]),"=r"((r)[6]),"=r"((r)[7]), \
          "=r"((r)[8]),"=r"((r)[9]),"=r"((r)[10]),"=r"((r)[11]),"=r"((r)[12]),"=r"((r)[13]),"=r"((r)[14]),"=r"((r)[15]), \
          "=r"((r)[16]),"=r"((r)[17]),"=r"((r)[18]),"=r"((r)[19]),"=r"((r)[20]),"=r"((r)[21]),"=r"((r)[22]),"=r"((r)[23]), \
          "=r"((r)[24]),"=r"((r)[25]),"=r"((r)[26]),"=r"((r)[27]),"=r"((r)[28]),"=r"((r)[29]),"=r"((r)[30]),"=r"((r)[31]) \
        : "r"(ta))
#endif // HAS_TCGEN05

#define STS128(a, r0, r1, r2, r3) \
    asm volatile("st.shared.v4.b32 [%0], {%1, %2, %3, %4};" :: "r"(a), "r"(r0), "r"(r1), "r"(r2), "r"(r3) : "memory")

// Volatile global loads — pinned in program order, ptxas cannot sink them.
#define LDGV(dst, p, IMM) \
    asm volatile("ld.global.nc.f32 %0, [%1+" #IMM "];" : "=f"(dst) : "l"(p))
#define LDGV4(dst, p) \
    asm volatile("ld.global.nc.v4.f32 {%0,%1,%2,%3}, [%4];" \
                 : "=f"((dst)[0]), "=f"((dst)[1]), "=f"((dst)[2]), "=f"((dst)[3]) : "l"(p))
// 16 column-strided loads (stride D*4 = 512B)
#define PREFETCH16(dst, base) do { \
    LDGV((dst)[0],  (base), 0);    LDGV((dst)[1],  (base), 512);  \
    LDGV((dst)[2],  (base), 1024); LDGV((dst)[3],  (base), 1536); \
    LDGV((dst)[4],  (base), 2048); LDGV((dst)[5],  (base), 2560); \
    LDGV((dst)[6],  (base), 3072); LDGV((dst)[7],  (base), 3584); \
    LDGV((dst)[8],  (base), 4096); LDGV((dst)[9],  (base), 4608); \
    LDGV((dst)[10], (base), 5120); LDGV((dst)[11], (base), 5632); \
    LDGV((dst)[12], (base), 6144); LDGV((dst)[13], (base), 6656); \
    LDGV((dst)[14], (base), 7168); LDGV((dst)[15], (base), 7680); \
} while (0)

// SMEM descriptor: SW128, version 1 (Blackwell), SBO=64, LBO=1
#define SMEM_DESC_BASE ((uint64_t(2)<<61) | (uint64_t(1)<<46) | (uint64_t(64)<<32) | (uint64_t(1)<<16))
#define MAKE_DESC(addr) (SMEM_DESC_BASE | ((uint64_t)((addr) >> 4) & 0x3FFF))
#define SWZ(b) ((b) ^ (((b) >> 3) & 0x70))

// byte offset for K-major tiles: 128 rows x 32 tf32 (128B rows)
__device__ __forceinline__ uint32_t koff(int row, int col) {
    uint32_t b = (uint32_t)row * 128u + (uint32_t)col * 4u;
    return SWZ(b);
}

__device__ __forceinline__ float phi(float x) { return x > 0.f ? x + 1.f : __expf(x); }

// Dekker truncation split: x = hi + lo with hi, lo tf32-representable.
__device__ __forceinline__ void split_tf32(float x, float& h, float& l) {
    h = __uint_as_float(__float_as_uint(x) & TF32_MASK);
    float lf = x - h;                 // exact
    l = __uint_as_float(__float_as_uint(lf) & TF32_MASK);
}

// ---------------------------------------------------------------------------
// kv_kernel: part[split][bh][e][d] = sum_kv V[kv][e]*phi(K[kv][d]); Zpart likewise
// Single-buffer smem stage; asm-volatile register prefetch; SPL=4; lb(256,3).
// ---------------------------------------------------------------------------
__global__ __launch_bounds__(256, 3) void kv_kernel(const float* __restrict__ K,
                                                    const float* __restrict__ V) {
    extern __shared__ char dyns[];
    const int tid = threadIdx.x;
    const int bh = blockIdx.x / SPL;
    const int split = blockIdx.x % SPL;
    const float* Kp = K + ((size_t)bh * KVLEN + (size_t)split * KVCHUNK) * D;
    const float* Vp = V + ((size_t)bh * KVLEN + (size_t)split * KVCHUNK) * D;

#if HAS_TCGEN05
    __shared__ uint32_t s_tmem;
    __shared__ __align__(8) unsigned long long s_mbar;
    __shared__ float sZ[D];
    const int wid = tid >> 5;

    uint32_t sbase = (smem_u32(dyns) + 1023u) & ~1023u;
    const uint32_t AH = sbase;             // V hi    [128 e][32 kv] tf32
    const uint32_t AL = sbase + 16384;     // V lo
    const uint32_t BHt = sbase + 32768;    // phiK hi [128 d][32 kv]
    const uint32_t BLt = sbase + 49152;    // phiK lo
    uint32_t mbar = smem_u32(&s_mbar);

    if (wid == 0) {
        TCGEN05_ALLOC(smem_u32(&s_tmem), 128);
        TCGEN05_RELINQ();
    }
    if (tid == 0) MBARRIER_INIT(mbar, 1);
    if (tid < D) sZ[tid] = 0.f;
    __syncthreads();
    const uint32_t tmem = s_tmem;

    const int lane_c = tid & 127;          // column: e for V, d for K
    const int g = tid >> 7;                // row half: rows g*16 .. g*16+15
    float zacc = 0.f;

    const uint64_t adesc = MAKE_DESC(AH), aldesc = MAKE_DESC(AL);
    const uint64_t bdesc = MAKE_DESC(BHt), bldesc = MAKE_DESC(BLt);

    float vV[16], vK[16];                  // prefetched RAW operands

    // prologue: volatile prefetch of chunk 0
    PREFETCH16(vV, Vp + (size_t)(g * 16) * D + lane_c);
    PREFETCH16(vK, Kp + (size_t)(g * 16) * D + lane_c);

    for (int chunk = 0; chunk < NCHUNK; chunk++) {
        // wait until MMAs of chunk-1 finished reading the stage
        if (chunk > 0) mbar_wait(mbar, (uint32_t)((chunk - 1) & 1));
        __syncthreads();

        // consume prefetched registers: phi (K side), split, STS
#pragma unroll
        for (int j = 0; j < 4; j++) {
            float h0, l0, h1, l1, h2, l2, h3, l3;
            split_tf32(vV[j*4+0], h0, l0);
            split_tf32(vV[j*4+1], h1, l1);
            split_tf32(vV[j*4+2], h2, l2);
            split_tf32(vV[j*4+3], h3, l3);
            uint32_t off = koff(lane_c, g * 16 + j * 4);
            STS128(AH + off, __float_as_uint(h0), __float_as_uint(h1),
                             __float_as_uint(h2), __float_as_uint(h3));
            STS128(AL + off, __float_as_uint(l0), __float_as_uint(l1),
                             __float_as_uint(l2), __float_as_uint(l3));
        }
#pragma unroll
        for (int j = 0; j < 4; j++) {
            float p0 = phi(vK[j*4+0]), p1 = phi(vK[j*4+1]);
            float p2 = phi(vK[j*4+2]), p3 = phi(vK[j*4+3]);
            zacc += p0 + p1 + p2 + p3;
            float h0, l0, h1, l1, h2, l2, h3, l3;
            split_tf32(p0, h0, l0); split_tf32(p1, h1, l1);
            split_tf32(p2, h2, l2); split_tf32(p3, h3, l3);
            uint32_t off = koff(lane_c, g * 16 + j * 4);
            STS128(BHt + off, __float_as_uint(h0), __float_as_uint(h1),
                              __float_as_uint(h2), __float_as_uint(h3));
            STS128(BLt + off, __float_as_uint(l0), __float_as_uint(l1),
                              __float_as_uint(l2), __float_as_uint(l3));
        }
        __syncthreads();
        FENCE_ASYNC_SHARED();

        if (wid == 0 && elect_one()) {
#pragma unroll
            for (int ks = 0; ks < 4; ks++) {          // 32 kv = 4 K8-steps
                uint64_t o = (uint64_t)(ks * 2);
                mma_tf32_ss(tmem, adesc + o, bdesc + o, !(chunk == 0 && ks == 0));
                mma_tf32_ss(tmem, adesc + o, bldesc + o, true);
                mma_tf32_ss(tmem, aldesc + o, bdesc + o, true);
            }
            TCGEN05_COMMIT(mbar);
        }

        // volatile prefetch of chunk+1 — flies during the MMA wait
        if (chunk + 1 < NCHUNK) {
            const int k0 = (chunk + 1) * TK + g * 16;
            PREFETCH16(vV, Vp + (size_t)k0 * D + lane_c);
            PREFETCH16(vK, Kp + (size_t)k0 * D + lane_c);
        }
    }

    atomicAdd(&sZ[lane_c], zacc);
    mbar_wait(mbar, (uint32_t)((NCHUNK - 1) & 1));
    TCGEN05_FENCE_AFTER();

    {   // epilogue: plain stores to this split's partial buffer
        const int sub = wid & 3;
        const int colbase = (wid >> 2) * 64;
        const int row = sub * 32 + (tid & 31);       // e
        float* dst = g_part + ((size_t)split * BH + bh) * D * D + (size_t)row * D;
#pragma unroll
        for (int cb = 0; cb < 64; cb += 32) {
            uint32_t r[32];
            LDTM_X32(r, tmem + colbase + cb);
            TCGEN05_WAIT_LD();
#pragma unroll
            for (int j4 = 0; j4 < 8; j4++) {
                float4 o;
                o.x = __uint_as_float(r[j4*4+0]);
                o.y = __uint_as_float(r[j4*4+1]);
                o.z = __uint_as_float(r[j4*4+2]);
                o.w = __uint_as_float(r[j4*4+3]);
                *(float4*)(dst + colbase + cb + j4*4) = o;
            }
        }
    }
    __syncthreads();
    if (tid < D)
        g_Zpart[(size_t)split * BH * D + (size_t)bh * D + tid] = sZ[tid];

    if (tid == 0) MBARRIER_INVAL(mbar);
    __syncthreads();
    if (wid == 0) TCGEN05_DEALLOC(tmem, 128);

#else  // ------------------- FFMA fallback -------------------
    const int FKT = 16;
    float* As = (float*)dyns;                 // [FKT][D] phiK
    float* Bs = As + FKT * D;                 // [FKT][D] V

    const int tx = tid & 15;                  // e group
    const int ty = tid >> 4;                  // d group

    float acc[8][8];
#pragma unroll
    for (int i = 0; i < 8; i++)
#pragma unroll
        for (int j = 0; j < 8; j++) acc[i][j] = 0.f;
    float zacc = 0.f;

    for (int k0 = 0; k0 < KVCHUNK; k0 += FKT) {
#pragma unroll
        for (int r = 0; r < 2; r++) {
            int idx = tid + r * 256;
            int row = idx >> 5;
            int c4 = (idx & 31) * 4;
            float4 kq = *(const float4*)(Kp + (size_t)(k0 + row) * D + c4);
            As[row * D + c4 + 0] = phi(kq.x);
            As[row * D + c4 + 1] = phi(kq.y);
            As[row * D + c4 + 2] = phi(kq.z);
            As[row * D + c4 + 3] = phi(kq.w);
            float4 vq = *(const float4*)(Vp + (size_t)(k0 + row) * D + c4);
            Bs[row * D + c4 + 0] = vq.x;
            Bs[row * D + c4 + 1] = vq.y;
            Bs[row * D + c4 + 2] = vq.z;
            Bs[row * D + c4 + 3] = vq.w;
        }
        __syncthreads();
#pragma unroll
        for (int kk = 0; kk < FKT; kk++) {
            float a[8], b[8];
#pragma unroll
            for (int i = 0; i < 8; i++) a[i] = As[kk * D + ty + 16 * i];
#pragma unroll
            for (int j = 0; j < 8; j++) b[j] = Bs[kk * D + tx + 16 * j];
#pragma unroll
            for (int i = 0; i < 8; i++)
#pragma unroll
                for (int j = 0; j < 8; j++) acc[i][j] = fmaf(a[i], b[j], acc[i][j]);
        }
        if (tid < D) {
            float s = 0.f;
#pragma unroll
            for (int kk = 0; kk < FKT; kk++) s += As[kk * D + tid];
            zacc += s;
        }
        __syncthreads();
    }

    float* dst = g_part + ((size_t)split * BH + bh) * D * D;
#pragma unroll
    for (int i = 0; i < 8; i++) {
        int drow = ty + 16 * i;
#pragma unroll
        for (int j = 0; j < 8; j++) {
            int ecol = tx + 16 * j;
            dst[(size_t)ecol * D + drow] = acc[i][j];   // transposed store
        }
    }
    if (tid < D)
        g_Zpart[(size_t)split * BH * D + (size_t)bh * D + tid] = zacc;
#endif
}

// ---------------------------------------------------------------------------
// reduce_kernel: sum SPL partials -> KVT hi/lo (tf32-masked) + Z
// ---------------------------------------------------------------------------
__global__ __launch_bounds__(256) void reduce_kernel() {
    const int gid = blockIdx.x * blockDim.x + threadIdx.x;
    const int n4 = BH * D * D / 4;
    const size_t stride4 = (size_t)BH * D * D / 4;
    const float4* P = (const float4*)g_part;
    float4* Hi = (float4*)g_KVThi;
    float4* Lo = (float4*)g_KVTlo;

    for (int i = gid; i < n4; i += gridDim.x * blockDim.x) {
        float4 s = P[i];
#pragma unroll
        for (int sp = 1; sp < SPL; sp++) {
            float4 p = P[(size_t)sp * stride4 + i];
            s.x += p.x; s.y += p.y; s.z += p.z; s.w += p.w;
        }
        float4 h, l;
        split_tf32(s.x, h.x, l.x);
        split_tf32(s.y, h.y, l.y);
        split_tf32(s.z, h.z, l.z);
        split_tf32(s.w, h.w, l.w);
        Hi[i] = h; Lo[i] = l;
    }

    const int nz = BH * D;
    for (int i = gid; i < nz; i += gridDim.x * blockDim.x) {
        float s = 0.f;
#pragma unroll
        for (int sp = 0; sp < SPL; sp++) s += g_Zpart[(size_t)sp * nz + i];
        g_Z[i] = s;
    }
}

// ---------------------------------------------------------------------------
// out_kernel: D2[q][e] = sum_d phiQ[q][d]*KVT[e][d]; out = D2 / (phiQ.Z + eps)
// Q d-chunks prefetched into registers (volatile) during the MMA wait.
// ---------------------------------------------------------------------------
__global__ __launch_bounds__(256, 3) void out_kernel(const float* __restrict__ Q,
                                                     float* __restrict__ out) {
    extern __shared__ char dyns[];
    __shared__ float Zs[D];
    __shared__ float sdenom[QT];

    const int tid = threadIdx.x;
    const int bh = blockIdx.y;
    const int q0 = blockIdx.x * QT;
    const float* Qp = Q + ((size_t)bh * QLEN + q0) * D;
    const float* KHp = g_KVThi + (size_t)bh * D * D;
    const float* KLp = g_KVTlo + (size_t)bh * D * D;
    float* outp = out + ((size_t)bh * QLEN + q0) * D;

    if (tid < D) Zs[tid] = g_Z[bh * D + tid];
    if (tid < QT) sdenom[tid] = 0.f;

#if HAS_TCGEN05
    __shared__ uint32_t s_tmem;
    __shared__ __align__(8) unsigned long long s_mbar;
    const int wid = tid >> 5;
    const int lane = tid & 31;

    uint32_t sbase = (smem_u32(dyns) + 1023u) & ~1023u;
    const uint32_t AH = sbase;              // phiQ hi [128 q][32 d]
    const uint32_t AL = sbase + 16384;
    const uint32_t BHt = sbase + 32768;     // KVT hi  [128 e][32 d]
    const uint32_t BLt = sbase + 49152;
    uint32_t mbar = smem_u32(&s_mbar);

    if (wid == 0) {
        TCGEN05_ALLOC(smem_u32(&s_tmem), 128);
        TCGEN05_RELINQ();
    }
    if (tid == 0) MBARRIER_INIT(mbar, 1);
    __syncthreads();
    const uint32_t tmem = s_tmem;

    const uint64_t ah = MAKE_DESC(AH), al = MAKE_DESC(AL);
    const uint64_t bb = MAKE_DESC(BHt), bl = MAKE_DESC(BLt);

    const int prow = tid >> 3;              // base row for this thread's slices
    const int pc4 = (tid & 7) * 4;          // column within the 32-d chunk

    float qv[16];                           // prefetched Q (4 rows x 4 floats)

    // prologue: volatile prefetch of d-chunk 0
#pragma unroll
    for (int s = 0; s < 4; s++)
        LDGV4(qv + s * 4, Qp + (size_t)(prow + 32 * s) * D + pc4);

    for (int it = 0; it < NDCH; it++) {
        if (it > 0) mbar_wait(mbar, (uint32_t)((it - 1) & 1));
        __syncthreads();

        const int d0 = it * DK;
        // consume prefetched Q: phi + denominator + split + STS
#pragma unroll
        for (int s = 0; s < 4; s++) {
            int row = prow + 32 * s;
            float p0 = phi(qv[s*4+0]), p1 = phi(qv[s*4+1]);
            float p2 = phi(qv[s*4+2]), p3 = phi(qv[s*4+3]);
            float dpart = p0 * Zs[d0 + pc4] + p1 * Zs[d0 + pc4 + 1]
                        + p2 * Zs[d0 + pc4 + 2] + p3 * Zs[d0 + pc4 + 3];
            dpart += __shfl_xor_sync(0xFFFFFFFFu, dpart, 4);
            dpart += __shfl_xor_sync(0xFFFFFFFFu, dpart, 2);
            dpart += __shfl_xor_sync(0xFFFFFFFFu, dpart, 1);
            if ((lane & 7) == 0) atomicAdd(&sdenom[row], dpart);
            float h0, l0, h1, l1, h2, l2, h3, l3;
            split_tf32(p0, h0, l0); split_tf32(p1, h1, l1);
            split_tf32(p2, h2, l2); split_tf32(p3, h3, l3);
            uint32_t off = koff(row, pc4);
            STS128(AH + off, __float_as_uint(h0), __float_as_uint(h1),
                             __float_as_uint(h2), __float_as_uint(h3));
            STS128(AL + off, __float_as_uint(l0), __float_as_uint(l1),
                             __float_as_uint(l2), __float_as_uint(l3));
        }
        // KVT tiles: pre-masked, pure copy (L2-resident)
#pragma unroll
        for (int s = 0; s < 4; s++) {
            int row = prow + 32 * s;
            uint32_t off = koff(row, pc4);
            float4 h = *(const float4*)(KHp + (size_t)row * D + d0 + pc4);
            STS128(BHt + off, __float_as_uint(h.x), __float_as_uint(h.y),
                              __float_as_uint(h.z), __float_as_uint(h.w));
            float4 l = *(const float4*)(KLp + (size_t)row * D + d0 + pc4);
            STS128(BLt + off, __float_as_uint(l.x), __float_as_uint(l.y),
                              __float_as_uint(l.z), __float_as_uint(l.w));
        }
        __syncthreads();
        FENCE_ASYNC_SHARED();

        if (wid == 0 && elect_one()) {
#pragma unroll
            for (int ks = 0; ks < 4; ks++) {
                uint64_t o = (uint64_t)(ks * 2);
                mma_tf32_ss(tmem, ah + o, bb + o, !(it == 0 && ks == 0));
                mma_tf32_ss(tmem, ah + o, bl + o, true);
                mma_tf32_ss(tmem, al + o, bb + o, true);
            }
            TCGEN05_COMMIT(mbar);
        }

        // volatile prefetch of next d-chunk — flies during the MMA wait
        if (it + 1 < NDCH) {
            const int dn = (it + 1) * DK;
#pragma unroll
            for (int s = 0; s < 4; s++)
                LDGV4(qv + s * 4, Qp + (size_t)(prow + 32 * s) * D + dn + pc4);
        }
    }

    mbar_wait(mbar, (uint32_t)((NDCH - 1) & 1));
    TCGEN05_FENCE_AFTER();
    __syncthreads();

    // epilogue: TMEM -> smem bounce (stride 129, conflict-free) -> coalesced STG
    float* sb = (float*)((char*)dyns + (sbase - smem_u32(dyns)));
    if (tid < QT) {
        const int row = tid;
        const float rd = 1.f / (sdenom[row] + EPS);
#pragma unroll
        for (int cb = 0; cb < 128; cb += 32) {
            uint32_t r[32];
            LDTM_X32(r, tmem + cb);
            TCGEN05_WAIT_LD();
#pragma unroll
            for (int j = 0; j < 32; j++)
                sb[row * 129 + cb + j] = __uint_as_float(r[j]) * rd;
        }
    }
    __syncthreads();

#pragma unroll
    for (int it = 0; it < 16; it++) {
        int idx = it * 256 + tid;
        int row = idx >> 5;
        int c4 = (idx & 31) * 4;
        float4 o;
        o.x = sb[row * 129 + c4];
        o.y = sb[row * 129 + c4 + 1];
        o.z = sb[row * 129 + c4 + 2];
        o.w = sb[row * 129 + c4 + 3];
        *(float4*)(outp + (size_t)row * D + c4) = o;
    }

    __syncthreads();
    if (tid == 0) MBARRIER_INVAL(mbar);
    __syncthreads();
    if (wid == 0) TCGEN05_DEALLOC(tmem, 128);

#else  // ------------------- FFMA fallback -------------------
    const int FKT = 16;
    float* Qs = (float*)dyns;                 // [128][17] phiQ chunk
    float* Ks = Qs + 128 * 17;                // [128][17] KVT chunk

    const int tx = tid & 15;                  // e group
    const int ty = tid >> 4;                  // q group

    float acc[8][8];
#pragma unroll
    for (int i = 0; i < 8; i++)
#pragma unroll
        for (int j = 0; j < 8; j++) acc[i][j] = 0.f;
    float dsum = 0.f;
    __syncthreads();

    for (int k0 = 0; k0 < D; k0 += FKT) {
#pragma unroll
        for (int r = 0; r < 2; r++) {
            int idx = tid + r * 256;
            int row = idx >> 2;
            int c4 = (idx & 3) * 4;
            float4 qv2 = *(const float4*)(Qp + (size_t)row * D + k0 + c4);
            Qs[row * 17 + c4 + 0] = phi(qv2.x);
            Qs[row * 17 + c4 + 1] = phi(qv2.y);
            Qs[row * 17 + c4 + 2] = phi(qv2.z);
            Qs[row * 17 + c4 + 3] = phi(qv2.w);
            float4 kh = *(const float4*)(KHp + (size_t)row * D + k0 + c4);
            float4 kl = *(const float4*)(KLp + (size_t)row * D + k0 + c4);
            Ks[row * 17 + c4 + 0] = kh.x + kl.x;
            Ks[row * 17 + c4 + 1] = kh.y + kl.y;
            Ks[row * 17 + c4 + 2] = kh.z + kl.z;
            Ks[row * 17 + c4 + 3] = kh.w + kl.w;
        }
        __syncthreads();
#pragma unroll
        for (int kk = 0; kk < FKT; kk++) {
            float a[8], b[8];
#pragma unroll
            for (int i = 0; i < 8; i++) a[i] = Qs[(ty + 16 * i) * 17 + kk];
#pragma unroll
            for (int j = 0; j < 8; j++) b[j] = Ks[(tx + 16 * j) * 17 + kk];
#pragma unroll
            for (int i = 0; i < 8; i++)
#pragma unroll
                for (int j = 0; j < 8; j++) acc[i][j] = fmaf(a[i], b[j], acc[i][j]);
        }
        if (tid < QT) {
            float s = 0.f;
#pragma unroll
            for (int kk = 0; kk < FKT; kk++) s += Qs[tid * 17 + kk] * Zs[k0 + kk];
            dsum += s;
        }
        __syncthreads();
    }

    if (tid < QT) sdenom[tid] = 1.f / (dsum + EPS);
    __syncthreads();

#pragma unroll
    for (int i = 0; i < 8; i++) {
        int row = ty + 16 * i;
        float rd = sdenom[row];
#pragma unroll
        for (int j = 0; j < 8; j++)
            outp[(size_t)row * D + tx + 16 * j] = acc[i][j] * rd;
    }
#endif
}

extern "C" void kernel_launch(void* const* d_in, const int* in_sizes, int n_in,
                              void* d_out, int out_size) {
    const float* Q = (const float*)d_in[0];
    const float* K = (const float*)d_in[1];
    const float* V = (const float*)d_in[2];
    float* out = (float*)d_out;

    cudaFuncSetAttribute(kv_kernel, cudaFuncAttributeMaxDynamicSharedMemorySize, 66560);
    cudaFuncSetAttribute(out_kernel, cudaFuncAttributeMaxDynamicSharedMemorySize, 67584);

    kv_kernel<<<BH * SPL, 256, 66560>>>(K, V);
    reduce_kernel<<<512, 256>>>();
    out_kernel<<<dim3(QLEN / QT, BH), 256, 67584>>>(Q, out);
}

// round 16
// speedup vs baseline: 1.2408x; 1.0514x over previous
#include <cuda_runtime.h>
#include <cuda_bf16.h>
#include <cstdint>

// Linear attention, fp32 I/O: out = (phi(Q) @ (phi(K)^T V)) / (phi(Q).Z + eps)
// B=2 H=32 q=2048 kv=8192 d=128.
// Fast path (sm_100a cubin): tcgen05 tf32 hi/lo Dekker split, fp32 TMEM acc.
//   kv_kernel: SPL=4, DEPTH-2 asm-volatile register prefetch (ping-pong reg
//   buffers, ~128 regs, lb(256,2)) -> load flight window spans a full iteration.
//   out_kernel: depth-1 Q prefetch (R15).
// Fallback (plain compute_100 PTX pass): FFMA register-tile GEMMs.

#define BH      64
#define QLEN    2048
#define KVLEN   8192
#define D       128
#define EPS     1e-6f

#define SPL     4                  // kv splits
#define KVCHUNK (KVLEN / SPL)      // 2048 rows per block
#define TK      32                 // kv tile depth per smem chunk (tf32)
#define NCHUNK  (KVCHUNK / TK)     // 64 (even — required by the 2x unroll)

#define QT      128                // q rows per out block
#define DK      32                 // d chunk in out kernel
#define NDCH    (D / DK)           // 4

#define TF32_MASK 0xFFFFE000u

// idesc: dtype F32, atype/btype TF32(2), N=128, M=128 ; K=8 per step
#define IDESC_TF32 ((1u<<4) | (2u<<7) | (2u<<10) | ((128u/8u)<<17) | ((128u/16u)<<24))

#if defined(__CUDA_ARCH_FEAT_SM100_ALL) || defined(__CUDA_ARCH_FEAT_SM101_ALL) || defined(__CUDA_ARCH_FEAT_SM103_ALL)
#define HAS_TCGEN05 1
#else
#define HAS_TCGEN05 0
#endif

__device__ float g_part[SPL * BH * D * D];   // per-split KVT partials, 16 MB
__device__ float g_Zpart[SPL * BH * D];
__device__ float g_KVThi[BH * D * D];        // tf32-masked hi, 4 MB
__device__ float g_KVTlo[BH * D * D];        // tf32-masked lo, 4 MB
__device__ float g_Z[BH * D];

// ---------------------------------------------------------------------------
// PTX helpers
// ---------------------------------------------------------------------------
__device__ __forceinline__ uint32_t smem_u32(const void* p) {
    uint32_t a;
    asm("{ .reg .u64 t; cvta.to.shared.u64 t, %1; cvt.u32.u64 %0, t; }" : "=r"(a) : "l"(p));
    return a;
}
__device__ __forceinline__ uint32_t elect_one() {
    uint32_t pred;
    asm volatile("{\n\t.reg .pred p;\n\telect.sync _|p, 0xFFFFFFFF;\n\tselp.b32 %0, 1, 0, p;\n\t}"
                 : "=r"(pred));
    return pred;
}

#if HAS_TCGEN05
#define TCGEN05_ALLOC(sa, n) \
    asm volatile("tcgen05.alloc.cta_group::1.sync.aligned.shared::cta.b32 [%0], %1;" \
                 :: "r"((uint32_t)(sa)), "r"((uint32_t)(n)) : "memory")
#define TCGEN05_DEALLOC(t, n) \
    asm volatile("tcgen05.dealloc.cta_group::1.sync.aligned.b32 %0, %1;" :: "r"(t), "r"((uint32_t)(n)))
#define TCGEN05_RELINQ() \
    asm volatile("tcgen05.relinquish_alloc_permit.cta_group::1.sync.aligned;")
#define TCGEN05_COMMIT(mb) \
    asm volatile("tcgen05.commit.cta_group::1.mbarrier::arrive::one.shared::cluster.b64 [%0];" \
                 :: "r"((uint32_t)(mb)) : "memory")
#define TCGEN05_FENCE_AFTER()  asm volatile("tcgen05.fence::after_thread_sync;" ::: "memory")
#define TCGEN05_WAIT_LD()      asm volatile("tcgen05.wait::ld.sync.aligned;" ::: "memory")
#define FENCE_ASYNC_SHARED()   asm volatile("fence.proxy.async.shared::cta;" ::: "memory")

#define MBARRIER_INIT(mb, cnt) \
    asm volatile("mbarrier.init.shared.b64 [%0], %1;" :: "r"((uint32_t)(mb)), "r"((uint32_t)(cnt)) : "memory")
#define MBARRIER_INVAL(mb) \
    asm volatile("mbarrier.inval.shared.b64 [%0];" :: "r"((uint32_t)(mb)) : "memory")

__device__ __forceinline__ void mbar_wait(uint32_t mb, uint32_t parity) {
    uint32_t done;
    asm volatile("{\n\t.reg .pred p;\n\t"
                 "mbarrier.try_wait.parity.acquire.cta.shared::cta.b64 p, [%1], %2;\n\t"
                 "selp.b32 %0, 1, 0, p;\n\t}" : "=r"(done) : "r"(mb), "r"(parity) : "memory");
    if (!done) {
        asm volatile("{\n\t.reg .pred P1;\n\t"
                     "WL_%=:\n\t"
                     "mbarrier.try_wait.parity.acquire.cta.shared::cta.b64 P1, [%0], %1, 0x989680;\n\t"
                     "@P1 bra.uni WD_%=;\n\t"
                     "bra.uni WL_%=;\n\t"
                     "WD_%=:\n\t}" :: "r"(mb), "r"(parity) : "memory");
    }
}

__device__ __forceinline__ void mma_tf32_ss(uint32_t d_tmem, uint64_t a_desc, uint64_t b_desc,
                                            bool acc) {
    uint32_t en = acc ? 1u : 0u;
    asm volatile("{\n\t.reg .pred p;\n\tsetp.ne.u32 p, %5, 0;\n\t"
                 "tcgen05.mma.cta_group::1.kind::tf32 [%0], %1, %2, %3, {%4, %4, %4, %4}, p;\n\t}"
                 :: "r"(d_tmem), "l"(a_desc), "l"(b_desc), "r"((uint32_t)IDESC_TF32), "r"(0u), "r"(en)
                 : "memory");
}

#define LDTM_X32(r, ta) \
    asm volatile("tcgen05.ld.sync.aligned.32x32b.x32.b32 " \
        "{%0,%1,%2,%3,%4,%5,%6,%7,%8,%9,%10,%11,%12,%13,%14,%15," \
        "%16,%17,%18,%19,%20,%21,%22,%23,%24,%25,%26,%27,%28,%29,%30,%31}, [%32];" \
        : "=r"((r)[0]),"=r"((r)[1]),"=r"((r)[2]),"=r"((r)[3]),"=r"((r)[4]),"=r"((r)[5]),"=r"((r)[6]),"=r"((r)[7]), \
          "=r"((r)[8]),"=r"((r)[9]),"=r"((r)[10]),"=r"((r)[11]),"=r"((r)[12]),"=r"((r)[13]),"=r"((r)[14]),"=r"((r)[15]), \
          "=r"((r)[16]),"=r"((r)[17]),"=r"((r)[18]),"=r"((r)[19]),"=r"((r)[20]),"=r"((r)[21]),"=r"((r)[22]),"=r"((r)[23]), \
          "=r"((r)[24]),"=r"((r)[25]),"=r"((r)[26]),"=r"((r)[27]),"=r"((r)[28]),"=r"((r)[29]),"=r"((r)[30]),"=r"((r)[31]) \
        : "r"(ta))
#endif // HAS_TCGEN05

#define STS128(a, r0, r1, r2, r3) \
    asm volatile("st.shared.v4.b32 [%0], {%1, %2, %3, %4};" :: "r"(a), "r"(r0), "r"(r1), "r"(r2), "r"(r3) : "memory")

// Volatile global loads — pinned in program order, ptxas cannot sink them.
#define LDGV(dst, p, IMM) \
    asm volatile("ld.global.nc.f32 %0, [%1+" #IMM "];" : "=f"(dst) : "l"(p))
#define LDGV4(dst, p) \
    asm volatile("ld.global.nc.v4.f32 {%0,%1,%2,%3}, [%4];" \
                 : "=f"((dst)[0]), "=f"((dst)[1]), "=f"((dst)[2]), "=f"((dst)[3]) : "l"(p))
// 16 column-strided loads (stride D*4 = 512B)
#define PREFETCH16(dst, base) do { \
    LDGV((dst)[0],  (base), 0);    LDGV((dst)[1],  (base), 512);  \
    LDGV((dst)[2],  (base), 1024); LDGV((dst)[3],  (base), 1536); \
    LDGV((dst)[4],  (base), 2048); LDGV((dst)[5],  (base), 2560); \
    LDGV((dst)[6],  (base), 3072); LDGV((dst)[7],  (base), 3584); \
    LDGV((dst)[8],  (base), 4096); LDGV((dst)[9],  (base), 4608); \
    LDGV((dst)[10], (base), 5120); LDGV((dst)[11], (base), 5632); \
    LDGV((dst)[12], (base), 6144); LDGV((dst)[13], (base), 6656); \
    LDGV((dst)[14], (base), 7168); LDGV((dst)[15], (base), 7680); \
} while (0)

// SMEM descriptor: SW128, version 1 (Blackwell), SBO=64, LBO=1
#define SMEM_DESC_BASE ((uint64_t(2)<<61) | (uint64_t(1)<<46) | (uint64_t(64)<<32) | (uint64_t(1)<<16))
#define MAKE_DESC(addr) (SMEM_DESC_BASE | ((uint64_t)((addr) >> 4) & 0x3FFF))
#define SWZ(b) ((b) ^ (((b) >> 3) & 0x70))

// byte offset for K-major tiles: 128 rows x 32 tf32 (128B rows)
__device__ __forceinline__ uint32_t koff(int row, int col) {
    uint32_t b = (uint32_t)row * 128u + (uint32_t)col * 4u;
    return SWZ(b);
}

__device__ __forceinline__ float phi(float x) { return x > 0.f ? x + 1.f : __expf(x); }

// Dekker truncation split: x = hi + lo with hi, lo tf32-representable.
__device__ __forceinline__ void split_tf32(float x, float& h, float& l) {
    h = __uint_as_float(__float_as_uint(x) & TF32_MASK);
    float lf = x - h;                 // exact
    l = __uint_as_float(__float_as_uint(lf) & TF32_MASK);
}

#if HAS_TCGEN05
// Consume one prefetched chunk from registers: split + STS into the stage.
__device__ __forceinline__ void kv_consume(const float* vV, const float* vK,
                                           float& zacc, int lane_c, int g,
                                           uint32_t AH, uint32_t AL,
                                           uint32_t BHt, uint32_t BLt) {
#pragma unroll
    for (int j = 0; j < 4; j++) {
        float h0, l0, h1, l1, h2, l2, h3, l3;
        split_tf32(vV[j*4+0], h0, l0);
        split_tf32(vV[j*4+1], h1, l1);
        split_tf32(vV[j*4+2], h2, l2);
        split_tf32(vV[j*4+3], h3, l3);
        uint32_t off = koff(lane_c, g * 16 + j * 4);
        STS128(AH + off, __float_as_uint(h0), __float_as_uint(h1),
                         __float_as_uint(h2), __float_as_uint(h3));
        STS128(AL + off, __float_as_uint(l0), __float_as_uint(l1),
                         __float_as_uint(l2), __float_as_uint(l3));
    }
#pragma unroll
    for (int j = 0; j < 4; j++) {
        float p0 = phi(vK[j*4+0]), p1 = phi(vK[j*4+1]);
        float p2 = phi(vK[j*4+2]), p3 = phi(vK[j*4+3]);
        zacc += p0 + p1 + p2 + p3;
        float h0, l0, h1, l1, h2, l2, h3, l3;
        split_tf32(p0, h0, l0); split_tf32(p1, h1, l1);
        split_tf32(p2, h2, l2); split_tf32(p3, h3, l3);
        uint32_t off = koff(lane_c, g * 16 + j * 4);
        STS128(BHt + off, __float_as_uint(h0), __float_as_uint(h1),
                          __float_as_uint(h2), __float_as_uint(h3));
        STS128(BLt + off, __float_as_uint(l0), __float_as_uint(l1),
                          __float_as_uint(l2), __float_as_uint(l3));
    }
}
#endif

// ---------------------------------------------------------------------------
// kv_kernel: part[split][bh][e][d] = sum_kv V[kv][e]*phi(K[kv][d]); Zpart likewise
// Single-buffer smem stage; DEPTH-2 register prefetch (ping-pong buffers).
// ---------------------------------------------------------------------------
__global__ __launch_bounds__(256, 2) void kv_kernel(const float* __restrict__ K,
                                                    const float* __restrict__ V) {
    extern __shared__ char dyns[];
    const int tid = threadIdx.x;
    const int bh = blockIdx.x / SPL;
    const int split = blockIdx.x % SPL;
    const float* Kp = K + ((size_t)bh * KVLEN + (size_t)split * KVCHUNK) * D;
    const float* Vp = V + ((size_t)bh * KVLEN + (size_t)split * KVCHUNK) * D;

#if HAS_TCGEN05
    __shared__ uint32_t s_tmem;
    __shared__ __align__(8) unsigned long long s_mbar;
    __shared__ float sZ[D];
    const int wid = tid >> 5;

    uint32_t sbase = (smem_u32(dyns) + 1023u) & ~1023u;
    const uint32_t AH = sbase;             // V hi    [128 e][32 kv] tf32
    const uint32_t AL = sbase + 16384;     // V lo
    const uint32_t BHt = sbase + 32768;    // phiK hi [128 d][32 kv]
    const uint32_t BLt = sbase + 49152;    // phiK lo
    uint32_t mbar = smem_u32(&s_mbar);

    if (wid == 0) {
        TCGEN05_ALLOC(smem_u32(&s_tmem), 128);
        TCGEN05_RELINQ();
    }
    if (tid == 0) MBARRIER_INIT(mbar, 1);
    if (tid < D) sZ[tid] = 0.f;
    __syncthreads();
    const uint32_t tmem = s_tmem;

    const int lane_c = tid & 127;          // column: e for V, d for K
    const int g = tid >> 7;                // row half: rows g*16 .. g*16+15
    float zacc = 0.f;

    const uint64_t adesc = MAKE_DESC(AH), aldesc = MAKE_DESC(AL);
    const uint64_t bdesc = MAKE_DESC(BHt), bldesc = MAKE_DESC(BLt);

    float aV[16], aK[16], bV[16], bK[16];  // ping-pong prefetch buffers

    // prologue: prefetch chunks 0 (A) and 1 (B)
    {
        const size_t rb = (size_t)(g * 16) * D + lane_c;
        PREFETCH16(aV, Vp + rb);
        PREFETCH16(aK, Kp + rb);
        PREFETCH16(bV, Vp + (size_t)TK * D + rb);
        PREFETCH16(bK, Kp + (size_t)TK * D + rb);
    }

    for (int c2 = 0; c2 < NCHUNK; c2 += 2) {
        // ---- chunk c2 (buffer A) ----
        if (c2 > 0) mbar_wait(mbar, (uint32_t)((c2 - 1) & 1));
        __syncthreads();
        kv_consume(aV, aK, zacc, lane_c, g, AH, AL, BHt, BLt);
        __syncthreads();
        FENCE_ASYNC_SHARED();
        if (wid == 0 && elect_one()) {
#pragma unroll
            for (int ks = 0; ks < 4; ks++) {
                uint64_t o = (uint64_t)(ks * 2);
                mma_tf32_ss(tmem, adesc + o, bdesc + o, !(c2 == 0 && ks == 0));
                mma_tf32_ss(tmem, adesc + o, bldesc + o, true);
                mma_tf32_ss(tmem, aldesc + o, bdesc + o, true);
            }
            TCGEN05_COMMIT(mbar);
        }
        if (c2 + 2 < NCHUNK) {
            const size_t rb = (size_t)((c2 + 2) * TK + g * 16) * D + lane_c;
            PREFETCH16(aV, Vp + rb);
            PREFETCH16(aK, Kp + rb);
        }

        // ---- chunk c2+1 (buffer B) ----
        mbar_wait(mbar, (uint32_t)(c2 & 1));
        __syncthreads();
        kv_consume(bV, bK, zacc, lane_c, g, AH, AL, BHt, BLt);
        __syncthreads();
        FENCE_ASYNC_SHARED();
        if (wid == 0 && elect_one()) {
#pragma unroll
            for (int ks = 0; ks < 4; ks++) {
                uint64_t o = (uint64_t)(ks * 2);
                mma_tf32_ss(tmem, adesc + o, bdesc + o, true);
                mma_tf32_ss(tmem, adesc + o, bldesc + o, true);
                mma_tf32_ss(tmem, aldesc + o, bdesc + o, true);
            }
            TCGEN05_COMMIT(mbar);
        }
        if (c2 + 3 < NCHUNK) {
            const size_t rb = (size_t)((c2 + 3) * TK + g * 16) * D + lane_c;
            PREFETCH16(bV, Vp + rb);
            PREFETCH16(bK, Kp + rb);
        }
    }

    atomicAdd(&sZ[lane_c], zacc);
    mbar_wait(mbar, (uint32_t)((NCHUNK - 1) & 1));
    TCGEN05_FENCE_AFTER();

    {   // epilogue: plain stores to this split's partial buffer
        const int sub = wid & 3;
        const int colbase = (wid >> 2) * 64;
        const int row = sub * 32 + (tid & 31);       // e
        float* dst = g_part + ((size_t)split * BH + bh) * D * D + (size_t)row * D;
#pragma unroll
        for (int cb = 0; cb < 64; cb += 32) {
            uint32_t r[32];
            LDTM_X32(r, tmem + colbase + cb);
            TCGEN05_WAIT_LD();
#pragma unroll
            for (int j4 = 0; j4 < 8; j4++) {
                float4 o;
                o.x = __uint_as_float(r[j4*4+0]);
                o.y = __uint_as_float(r[j4*4+1]);
                o.z = __uint_as_float(r[j4*4+2]);
                o.w = __uint_as_float(r[j4*4+3]);
                *(float4*)(dst + colbase + cb + j4*4) = o;
            }
        }
    }
    __syncthreads();
    if (tid < D)
        g_Zpart[(size_t)split * BH * D + (size_t)bh * D + tid] = sZ[tid];

    if (tid == 0) MBARRIER_INVAL(mbar);
    __syncthreads();
    if (wid == 0) TCGEN05_DEALLOC(tmem, 128);

#else  // ------------------- FFMA fallback -------------------
    const int FKT = 16;
    float* As = (float*)dyns;                 // [FKT][D] phiK
    float* Bs = As + FKT * D;                 // [FKT][D] V

    const int tx = tid & 15;                  // e group
    const int ty = tid >> 4;                  // d group

    float acc[8][8];
#pragma unroll
    for (int i = 0; i < 8; i++)
#pragma unroll
        for (int j = 0; j < 8; j++) acc[i][j] = 0.f;
    float zacc = 0.f;

    for (int k0 = 0; k0 < KVCHUNK; k0 += FKT) {
#pragma unroll
        for (int r = 0; r < 2; r++) {
            int idx = tid + r * 256;
            int row = idx >> 5;
            int c4 = (idx & 31) * 4;
            float4 kq = *(const float4*)(Kp + (size_t)(k0 + row) * D + c4);
            As[row * D + c4 + 0] = phi(kq.x);
            As[row * D + c4 + 1] = phi(kq.y);
            As[row * D + c4 + 2] = phi(kq.z);
            As[row * D + c4 + 3] = phi(kq.w);
            float4 vq = *(const float4*)(Vp + (size_t)(k0 + row) * D + c4);
            Bs[row * D + c4 + 0] = vq.x;
            Bs[row * D + c4 + 1] = vq.y;
            Bs[row * D + c4 + 2] = vq.z;
            Bs[row * D + c4 + 3] = vq.w;
        }
        __syncthreads();
#pragma unroll
        for (int kk = 0; kk < FKT; kk++) {
            float a[8], b[8];
#pragma unroll
            for (int i = 0; i < 8; i++) a[i] = As[kk * D + ty + 16 * i];
#pragma unroll
            for (int j = 0; j < 8; j++) b[j] = Bs[kk * D + tx + 16 * j];
#pragma unroll
            for (int i = 0; i < 8; i++)
#pragma unroll
                for (int j = 0; j < 8; j++) acc[i][j] = fmaf(a[i], b[j], acc[i][j]);
        }
        if (tid < D) {
            float s = 0.f;
#pragma unroll
            for (int kk = 0; kk < FKT; kk++) s += As[kk * D + tid];
            zacc += s;
        }
        __syncthreads();
    }

    float* dst = g_part + ((size_t)split * BH + bh) * D * D;
#pragma unroll
    for (int i = 0; i < 8; i++) {
        int drow = ty + 16 * i;
#pragma unroll
        for (int j = 0; j < 8; j++) {
            int ecol = tx + 16 * j;
            dst[(size_t)ecol * D + drow] = acc[i][j];   // transposed store
        }
    }
    if (tid < D)
        g_Zpart[(size_t)split * BH * D + (size_t)bh * D + tid] = zacc;
#endif
}

// ---------------------------------------------------------------------------
// reduce_kernel: sum SPL partials -> KVT hi/lo (tf32-masked) + Z
// ---------------------------------------------------------------------------
__global__ __launch_bounds__(256) void reduce_kernel() {
    const int gid = blockIdx.x * blockDim.x + threadIdx.x;
    const int n4 = BH * D * D / 4;
    const size_t stride4 = (size_t)BH * D * D / 4;
    const float4* P = (const float4*)g_part;
    float4* Hi = (float4*)g_KVThi;
    float4* Lo = (float4*)g_KVTlo;

    for (int i = gid; i < n4; i += gridDim.x * blockDim.x) {
        float4 s = P[i];
#pragma unroll
        for (int sp = 1; sp < SPL; sp++) {
            float4 p = P[(size_t)sp * stride4 + i];
            s.x += p.x; s.y += p.y; s.z += p.z; s.w += p.w;
        }
        float4 h, l;
        split_tf32(s.x, h.x, l.x);
        split_tf32(s.y, h.y, l.y);
        split_tf32(s.z, h.z, l.z);
        split_tf32(s.w, h.w, l.w);
        Hi[i] = h; Lo[i] = l;
    }

    const int nz = BH * D;
    for (int i = gid; i < nz; i += gridDim.x * blockDim.x) {
        float s = 0.f;
#pragma unroll
        for (int sp = 0; sp < SPL; sp++) s += g_Zpart[(size_t)sp * nz + i];
        g_Z[i] = s;
    }
}

// ---------------------------------------------------------------------------
// out_kernel: D2[q][e] = sum_d phiQ[q][d]*KVT[e][d]; out = D2 / (phiQ.Z + eps)
// Q d-chunks prefetched into registers (volatile) during the MMA wait.
// ---------------------------------------------------------------------------
__global__ __launch_bounds__(256, 3) void out_kernel(const float* __restrict__ Q,
                                                     float* __restrict__ out) {
    extern __shared__ char dyns[];
    __shared__ float Zs[D];
    __shared__ float sdenom[QT];

    const int tid = threadIdx.x;
    const int bh = blockIdx.y;
    const int q0 = blockIdx.x * QT;
    const float* Qp = Q + ((size_t)bh * QLEN + q0) * D;
    const float* KHp = g_KVThi + (size_t)bh * D * D;
    const float* KLp = g_KVTlo + (size_t)bh * D * D;
    float* outp = out + ((size_t)bh * QLEN + q0) * D;

    if (tid < D) Zs[tid] = g_Z[bh * D + tid];
    if (tid < QT) sdenom[tid] = 0.f;

#if HAS_TCGEN05
    __shared__ uint32_t s_tmem;
    __shared__ __align__(8) unsigned long long s_mbar;
    const int wid = tid >> 5;
    const int lane = tid & 31;

    uint32_t sbase = (smem_u32(dyns) + 1023u) & ~1023u;
    const uint32_t AH = sbase;              // phiQ hi [128 q][32 d]
    const uint32_t AL = sbase + 16384;
    const uint32_t BHt = sbase + 32768;     // KVT hi  [128 e][32 d]
    const uint32_t BLt = sbase + 49152;
    uint32_t mbar = smem_u32(&s_mbar);

    if (wid == 0) {
        TCGEN05_ALLOC(smem_u32(&s_tmem), 128);
        TCGEN05_RELINQ();
    }
    if (tid == 0) MBARRIER_INIT(mbar, 1);
    __syncthreads();
    const uint32_t tmem = s_tmem;

    const uint64_t ah = MAKE_DESC(AH), al = MAKE_DESC(AL);
    const uint64_t bb = MAKE_DESC(BHt), bl = MAKE_DESC(BLt);

    const int prow = tid >> 3;              // base row for this thread's slices
    const int pc4 = (tid & 7) * 4;          // column within the 32-d chunk

    float qv[16];                           // prefetched Q (4 rows x 4 floats)

    // prologue: volatile prefetch of d-chunk 0
#pragma unroll
    for (int s = 0; s < 4; s++)
        LDGV4(qv + s * 4, Qp + (size_t)(prow + 32 * s) * D + pc4);

    for (int it = 0; it < NDCH; it++) {
        if (it > 0) mbar_wait(mbar, (uint32_t)((it - 1) & 1));
        __syncthreads();

        const int d0 = it * DK;
        // consume prefetched Q: phi + denominator + split + STS
#pragma unroll
        for (int s = 0; s < 4; s++) {
            int row = prow + 32 * s;
            float p0 = phi(qv[s*4+0]), p1 = phi(qv[s*4+1]);
            float p2 = phi(qv[s*4+2]), p3 = phi(qv[s*4+3]);
            float dpart = p0 * Zs[d0 + pc4] + p1 * Zs[d0 + pc4 + 1]
                        + p2 * Zs[d0 + pc4 + 2] + p3 * Zs[d0 + pc4 + 3];
            dpart += __shfl_xor_sync(0xFFFFFFFFu, dpart, 4);
            dpart += __shfl_xor_sync(0xFFFFFFFFu, dpart, 2);
            dpart += __shfl_xor_sync(0xFFFFFFFFu, dpart, 1);
            if ((lane & 7) == 0) atomicAdd(&sdenom[row], dpart);
            float h0, l0, h1, l1, h2, l2, h3, l3;
            split_tf32(p0, h0, l0); split_tf32(p1, h1, l1);
            split_tf32(p2, h2, l2); split_tf32(p3, h3, l3);
            uint32_t off = koff(row, pc4);
            STS128(AH + off, __float_as_uint(h0), __float_as_uint(h1),
                             __float_as_uint(h2), __float_as_uint(h3));
            STS128(AL + off, __float_as_uint(l0), __float_as_uint(l1),
                             __float_as_uint(l2), __float_as_uint(l3));
        }
        // KVT tiles: pre-masked, pure copy (L2-resident)
#pragma unroll
        for (int s = 0; s < 4; s++) {
            int row = prow + 32 * s;
            uint32_t off = koff(row, pc4);
            float4 h = *(const float4*)(KHp + (size_t)row * D + d0 + pc4);
            STS128(BHt + off, __float_as_uint(h.x), __float_as_uint(h.y),
                              __float_as_uint(h.z), __float_as_uint(h.w));
            float4 l = *(const float4*)(KLp + (size_t)row * D + d0 + pc4);
            STS128(BLt + off, __float_as_uint(l.x), __float_as_uint(l.y),
                              __float_as_uint(l.z), __float_as_uint(l.w));
        }
        __syncthreads();
        FENCE_ASYNC_SHARED();

        if (wid == 0 && elect_one()) {
#pragma unroll
            for (int ks = 0; ks < 4; ks++) {
                uint64_t o = (uint64_t)(ks * 2);
                mma_tf32_ss(tmem, ah + o, bb + o, !(it == 0 && ks == 0));
                mma_tf32_ss(tmem, ah + o, bl + o, true);
                mma_tf32_ss(tmem, al + o, bb + o, true);
            }
            TCGEN05_COMMIT(mbar);
        }

        // volatile prefetch of next d-chunk — flies during the MMA wait
        if (it + 1 < NDCH) {
            const int dn = (it + 1) * DK;
#pragma unroll
            for (int s = 0; s < 4; s++)
                LDGV4(qv + s * 4, Qp + (size_t)(prow + 32 * s) * D + dn + pc4);
        }
    }

    mbar_wait(mbar, (uint32_t)((NDCH - 1) & 1));
    TCGEN05_FENCE_AFTER();
    __syncthreads();

    // epilogue: TMEM -> smem bounce (stride 129, conflict-free) -> coalesced STG
    float* sb = (float*)((char*)dyns + (sbase - smem_u32(dyns)));
    if (tid < QT) {
        const int row = tid;
        const float rd = 1.f / (sdenom[row] + EPS);
#pragma unroll
        for (int cb = 0; cb < 128; cb += 32) {
            uint32_t r[32];
            LDTM_X32(r, tmem + cb);
            TCGEN05_WAIT_LD();
#pragma unroll
            for (int j = 0; j < 32; j++)
                sb[row * 129 + cb + j] = __uint_as_float(r[j]) * rd;
        }
    }
    __syncthreads();

#pragma unroll
    for (int it = 0; it < 16; it++) {
        int idx = it * 256 + tid;
        int row = idx >> 5;
        int c4 = (idx & 31) * 4;
        float4 o;
        o.x = sb[row * 129 + c4];
        o.y = sb[row * 129 + c4 + 1];
        o.z = sb[row * 129 + c4 + 2];
        o.w = sb[row * 129 + c4 + 3];
        *(float4*)(outp + (size_t)row * D + c4) = o;
    }

    __syncthreads();
    if (tid == 0) MBARRIER_INVAL(mbar);
    __syncthreads();
    if (wid == 0) TCGEN05_DEALLOC(tmem, 128);

#else  // ------------------- FFMA fallback -------------------
    const int FKT = 16;
    float* Qs = (float*)dyns;                 // [128][17] phiQ chunk
    float* Ks = Qs + 128 * 17;                // [128][17] KVT chunk

    const int tx = tid & 15;                  // e group
    const int ty = tid >> 4;                  // q group

    float acc[8][8];
#pragma unroll
    for (int i = 0; i < 8; i++)
#pragma unroll
        for (int j = 0; j < 8; j++) acc[i][j] = 0.f;
    float dsum = 0.f;
    __syncthreads();

    for (int k0 = 0; k0 < D; k0 += FKT) {
#pragma unroll
        for (int r = 0; r < 2; r++) {
            int idx = tid + r * 256;
            int row = idx >> 2;
            int c4 = (idx & 3) * 4;
            float4 qv2 = *(const float4*)(Qp + (size_t)row * D + k0 + c4);
            Qs[row * 17 + c4 + 0] = phi(qv2.x);
            Qs[row * 17 + c4 + 1] = phi(qv2.y);
            Qs[row * 17 + c4 + 2] = phi(qv2.z);
            Qs[row * 17 + c4 + 3] = phi(qv2.w);
            float4 kh = *(const float4*)(KHp + (size_t)row * D + k0 + c4);
            float4 kl = *(const float4*)(KLp + (size_t)row * D + k0 + c4);
            Ks[row * 17 + c4 + 0] = kh.x + kl.x;
            Ks[row * 17 + c4 + 1] = kh.y + kl.y;
            Ks[row * 17 + c4 + 2] = kh.z + kl.z;
            Ks[row * 17 + c4 + 3] = kh.w + kl.w;
        }
        __syncthreads();
#pragma unroll
        for (int kk = 0; kk < FKT; kk++) {
            float a[8], b[8];
#pragma unroll
            for (int i = 0; i < 8; i++) a[i] = Qs[(ty + 16 * i) * 17 + kk];
#pragma unroll
            for (int j = 0; j < 8; j++) b[j] = Ks[(tx + 16 * j) * 17 + kk];
#pragma unroll
            for (int i = 0; i < 8; i++)
#pragma unroll
                for (int j = 0; j < 8; j++) acc[i][j] = fmaf(a[i], b[j], acc[i][j]);
        }
        if (tid < QT) {
            float s = 0.f;
#pragma unroll
            for (int kk = 0; kk < FKT; kk++) s += Qs[tid * 17 + kk] * Zs[k0 + kk];
            dsum += s;
        }
        __syncthreads();
    }

    if (tid < QT) sdenom[tid] = 1.f / (dsum + EPS);
    __syncthreads();

#pragma unroll
    for (int i = 0; i < 8; i++) {
        int row = ty + 16 * i;
        float rd = sdenom[row];
#pragma unroll
        for (int j = 0; j < 8; j++)
            outp[(size_t)row * D + tx + 16 * j] = acc[i][j] * rd;
    }
#endif
}

extern "C" void kernel_launch(void* const* d_in, const int* in_sizes, int n_in,
                              void* d_out, int out_size) {
    const float* Q = (const float*)d_in[0];
    const float* K = (const float*)d_in[1];
    const float* V = (const float*)d_in[2];
    float* out = (float*)d_out;

    cudaFuncSetAttribute(kv_kernel, cudaFuncAttributeMaxDynamicSharedMemorySize, 66560);
    cudaFuncSetAttribute(out_kernel, cudaFuncAttributeMaxDynamicSharedMemorySize, 67584);

    kv_kernel<<<BH * SPL, 256, 66560>>>(K, V);
    reduce_kernel<<<512, 256>>>();
    out_kernel<<<dim3(QLEN / QT, BH), 256, 67584>>>(Q, out);
}

// round 17
// speedup vs baseline: 1.3338x; 1.0749x over previous
#include <cuda_runtime.h>
#include <cuda_bf16.h>
#include <cstdint>

// Linear attention, fp32 I/O: out = (phi(Q) @ (phi(K)^T V)) / (phi(Q).Z + eps)
// B=2 H=32 q=2048 kv=8192 d=128.
// Fast path (sm_100a cubin): tcgen05 tf32 hi/lo Dekker split, fp32 TMEM acc.
//   kv_kernel: SPL=4, depth-2 asm-volatile register prefetch (R16 config).
//   out_kernel: N=256 MMA (A=KVT M=128, B=phiQ N=256), 512 CTAs, coalesced
//   direct-STG epilogue (no smem bounce), Q register prefetch.
// Fallback (plain compute_100 PTX pass): FFMA register-tile GEMMs.

#define BH      64
#define QLEN    2048
#define KVLEN   8192
#define D       128
#define EPS     1e-6f

#define SPL     4                  // kv splits
#define KVCHUNK (KVLEN / SPL)      // 2048 rows per block
#define TK      32                 // kv tile depth per smem chunk (tf32)
#define NCHUNK  (KVCHUNK / TK)     // 64 (even — required by the 2x unroll)

#define QT2     256                // q rows per out block (MMA N)
#define DK      32                 // d chunk in out kernel
#define NDCH    (D / DK)           // 4

#define TF32_MASK 0xFFFFE000u

// idesc: dtype F32, atype/btype TF32(2), M=128 ; K=8 per step
#define IDESC_N128 ((1u<<4) | (2u<<7) | (2u<<10) | ((128u/8u)<<17) | ((128u/16u)<<24))
#define IDESC_N256 ((1u<<4) | (2u<<7) | (2u<<10) | ((256u/8u)<<17) | ((128u/16u)<<24))

#if defined(__CUDA_ARCH_FEAT_SM100_ALL) || defined(__CUDA_ARCH_FEAT_SM101_ALL) || defined(__CUDA_ARCH_FEAT_SM103_ALL)
#define HAS_TCGEN05 1
#else
#define HAS_TCGEN05 0
#endif

__device__ float g_part[SPL * BH * D * D];   // per-split KVT partials, 16 MB
__device__ float g_Zpart[SPL * BH * D];
__device__ float g_KVThi[BH * D * D];        // tf32-masked hi, 4 MB
__device__ float g_KVTlo[BH * D * D];        // tf32-masked lo, 4 MB
__device__ float g_Z[BH * D];

// ---------------------------------------------------------------------------
// PTX helpers
// ---------------------------------------------------------------------------
__device__ __forceinline__ uint32_t smem_u32(const void* p) {
    uint32_t a;
    asm("{ .reg .u64 t; cvta.to.shared.u64 t, %1; cvt.u32.u64 %0, t; }" : "=r"(a) : "l"(p));
    return a;
}
__device__ __forceinline__ uint32_t elect_one() {
    uint32_t pred;
    asm volatile("{\n\t.reg .pred p;\n\telect.sync _|p, 0xFFFFFFFF;\n\tselp.b32 %0, 1, 0, p;\n\t}"
                 : "=r"(pred));
    return pred;
}

#if HAS_TCGEN05
#define TCGEN05_ALLOC(sa, n) \
    asm volatile("tcgen05.alloc.cta_group::1.sync.aligned.shared::cta.b32 [%0], %1;" \
                 :: "r"((uint32_t)(sa)), "r"((uint32_t)(n)) : "memory")
#define TCGEN05_DEALLOC(t, n) \
    asm volatile("tcgen05.dealloc.cta_group::1.sync.aligned.b32 %0, %1;" :: "r"(t), "r"((uint32_t)(n)))
#define TCGEN05_RELINQ() \
    asm volatile("tcgen05.relinquish_alloc_permit.cta_group::1.sync.aligned;")
#define TCGEN05_COMMIT(mb) \
    asm volatile("tcgen05.commit.cta_group::1.mbarrier::arrive::one.shared::cluster.b64 [%0];" \
                 :: "r"((uint32_t)(mb)) : "memory")
#define TCGEN05_FENCE_AFTER()  asm volatile("tcgen05.fence::after_thread_sync;" ::: "memory")
#define TCGEN05_WAIT_LD()      asm volatile("tcgen05.wait::ld.sync.aligned;" ::: "memory")
#define FENCE_ASYNC_SHARED()   asm volatile("fence.proxy.async.shared::cta;" ::: "memory")

#define MBARRIER_INIT(mb, cnt) \
    asm volatile("mbarrier.init.shared.b64 [%0], %1;" :: "r"((uint32_t)(mb)), "r"((uint32_t)(cnt)) : "memory")
#define MBARRIER_INVAL(mb) \
    asm volatile("mbarrier.inval.shared.b64 [%0];" :: "r"((uint32_t)(mb)) : "memory")

__device__ __forceinline__ void mbar_wait(uint32_t mb, uint32_t parity) {
    uint32_t done;
    asm volatile("{\n\t.reg .pred p;\n\t"
                 "mbarrier.try_wait.parity.acquire.cta.shared::cta.b64 p, [%1], %2;\n\t"
                 "selp.b32 %0, 1, 0, p;\n\t}" : "=r"(done) : "r"(mb), "r"(parity) : "memory");
    if (!done) {
        asm volatile("{\n\t.reg .pred P1;\n\t"
                     "WL_%=:\n\t"
                     "mbarrier.try_wait.parity.acquire.cta.shared::cta.b64 P1, [%0], %1, 0x989680;\n\t"
                     "@P1 bra.uni WD_%=;\n\t"
                     "bra.uni WL_%=;\n\t"
                     "WD_%=:\n\t}" :: "r"(mb), "r"(parity) : "memory");
    }
}

__device__ __forceinline__ void mma_tf32_ss(uint32_t d_tmem, uint64_t a_desc, uint64_t b_desc,
                                            uint32_t idesc, bool acc) {
    uint32_t en = acc ? 1u : 0u;
    asm volatile("{\n\t.reg .pred p;\n\tsetp.ne.u32 p, %5, 0;\n\t"
                 "tcgen05.mma.cta_group::1.kind::tf32 [%0], %1, %2, %3, {%4, %4, %4, %4}, p;\n\t}"
                 :: "r"(d_tmem), "l"(a_desc), "l"(b_desc), "r"(idesc), "r"(0u), "r"(en)
                 : "memory");
}

#define LDTM_X32(r, ta) \
    asm volatile("tcgen05.ld.sync.aligned.32x32b.x32.b32 " \
        "{%0,%1,%2,%3,%4,%5,%6,%7,%8,%9,%10,%11,%12,%13,%14,%15," \
        "%16,%17,%18,%19,%20,%21,%22,%23,%24,%25,%26,%27,%28,%29,%30,%31}, [%32];" \
        : "=r"((r)[0]),"=r"((r)[1]),"=r"((r)[2]),"=r"((r)[3]),"=r"((r)[4]),"=r"((r)[5]),"=r"((r)[6]),"=r"((r)[7]), \
          "=r"((r)[8]),"=r"((r)[9]),"=r"((r)[10]),"=r"((r)[11]),"=r"((r)[12]),"=r"((r)[13]),"=r"((r)[14]),"=r"((r)[15]), \
          "=r"((r)[16]),"=r"((r)[17]),"=r"((r)[18]),"=r"((r)[19]),"=r"((r)[20]),"=r"((r)[21]),"=r"((r)[22]),"=r"((r)[23]), \
          "=r"((r)[24]),"=r"((r)[25]),"=r"((r)[26]),"=r"((r)[27]),"=r"((r)[28]),"=r"((r)[29]),"=r"((r)[30]),"=r"((r)[31]) \
        : "r"(ta))
#endif // HAS_TCGEN05

#define STS128(a, r0, r1, r2, r3) \
    asm volatile("st.shared.v4.b32 [%0], {%1, %2, %3, %4};" :: "r"(a), "r"(r0), "r"(r1), "r"(r2), "r"(r3) : "memory")

// Volatile global loads — pinned in program order, ptxas cannot sink them.
#define LDGV(dst, p, IMM) \
    asm volatile("ld.global.nc.f32 %0, [%1+" #IMM "];" : "=f"(dst) : "l"(p))
#define LDGV4(dst, p) \
    asm volatile("ld.global.nc.v4.f32 {%0,%1,%2,%3}, [%4];" \
                 : "=f"((dst)[0]), "=f"((dst)[1]), "=f"((dst)[2]), "=f"((dst)[3]) : "l"(p))
// 16 column-strided loads (stride D*4 = 512B)
#define PREFETCH16(dst, base) do { \
    LDGV((dst)[0],  (base), 0);    LDGV((dst)[1],  (base), 512);  \
    LDGV((dst)[2],  (base), 1024); LDGV((dst)[3],  (base), 1536); \
    LDGV((dst)[4],  (base), 2048); LDGV((dst)[5],  (base), 2560); \
    LDGV((dst)[6],  (base), 3072); LDGV((dst)[7],  (base), 3584); \
    LDGV((dst)[8],  (base), 4096); LDGV((dst)[9],  (base), 4608); \
    LDGV((dst)[10], (base), 5120); LDGV((dst)[11], (base), 5632); \
    LDGV((dst)[12], (base), 6144); LDGV((dst)[13], (base), 6656); \
    LDGV((dst)[14], (base), 7168); LDGV((dst)[15], (base), 7680); \
} while (0)

// SMEM descriptor: SW128, version 1 (Blackwell), SBO=64, LBO=1
#define SMEM_DESC_BASE ((uint64_t(2)<<61) | (uint64_t(1)<<46) | (uint64_t(64)<<32) | (uint64_t(1)<<16))
#define MAKE_DESC(addr) (SMEM_DESC_BASE | ((uint64_t)((addr) >> 4) & 0x3FFF))
#define SWZ(b) ((b) ^ (((b) >> 3) & 0x70))

// byte offset for K-major tiles with 128B rows
__device__ __forceinline__ uint32_t koff(int row, int col) {
    uint32_t b = (uint32_t)row * 128u + (uint32_t)col * 4u;
    return SWZ(b);
}

__device__ __forceinline__ float phi(float x) { return x > 0.f ? x + 1.f : __expf(x); }

// Dekker truncation split: x = hi + lo with hi, lo tf32-representable.
__device__ __forceinline__ void split_tf32(float x, float& h, float& l) {
    h = __uint_as_float(__float_as_uint(x) & TF32_MASK);
    float lf = x - h;                 // exact
    l = __uint_as_float(__float_as_uint(lf) & TF32_MASK);
}

#if HAS_TCGEN05
// Consume one prefetched chunk from registers: split + STS into the stage.
__device__ __forceinline__ void kv_consume(const float* vV, const float* vK,
                                           float& zacc, int lane_c, int g,
                                           uint32_t AH, uint32_t AL,
                                           uint32_t BHt, uint32_t BLt) {
#pragma unroll
    for (int j = 0; j < 4; j++) {
        float h0, l0, h1, l1, h2, l2, h3, l3;
        split_tf32(vV[j*4+0], h0, l0);
        split_tf32(vV[j*4+1], h1, l1);
        split_tf32(vV[j*4+2], h2, l2);
        split_tf32(vV[j*4+3], h3, l3);
        uint32_t off = koff(lane_c, g * 16 + j * 4);
        STS128(AH + off, __float_as_uint(h0), __float_as_uint(h1),
                         __float_as_uint(h2), __float_as_uint(h3));
        STS128(AL + off, __float_as_uint(l0), __float_as_uint(l1),
                         __float_as_uint(l2), __float_as_uint(l3));
    }
#pragma unroll
    for (int j = 0; j < 4; j++) {
        float p0 = phi(vK[j*4+0]), p1 = phi(vK[j*4+1]);
        float p2 = phi(vK[j*4+2]), p3 = phi(vK[j*4+3]);
        zacc += p0 + p1 + p2 + p3;
        float h0, l0, h1, l1, h2, l2, h3, l3;
        split_tf32(p0, h0, l0); split_tf32(p1, h1, l1);
        split_tf32(p2, h2, l2); split_tf32(p3, h3, l3);
        uint32_t off = koff(lane_c, g * 16 + j * 4);
        STS128(BHt + off, __float_as_uint(h0), __float_as_uint(h1),
                          __float_as_uint(h2), __float_as_uint(h3));
        STS128(BLt + off, __float_as_uint(l0), __float_as_uint(l1),
                          __float_as_uint(l2), __float_as_uint(l3));
    }
}
#endif

// ---------------------------------------------------------------------------
// kv_kernel: part[split][bh][e][d] = sum_kv V[kv][e]*phi(K[kv][d]); Zpart likewise
// Single-buffer smem stage; DEPTH-2 register prefetch (ping-pong buffers).
// ---------------------------------------------------------------------------
__global__ __launch_bounds__(256, 2) void kv_kernel(const float* __restrict__ K,
                                                    const float* __restrict__ V) {
    extern __shared__ char dyns[];
    const int tid = threadIdx.x;
    const int bh = blockIdx.x / SPL;
    const int split = blockIdx.x % SPL;
    const float* Kp = K + ((size_t)bh * KVLEN + (size_t)split * KVCHUNK) * D;
    const float* Vp = V + ((size_t)bh * KVLEN + (size_t)split * KVCHUNK) * D;

#if HAS_TCGEN05
    __shared__ uint32_t s_tmem;
    __shared__ __align__(8) unsigned long long s_mbar;
    __shared__ float sZ[D];
    const int wid = tid >> 5;

    uint32_t sbase = (smem_u32(dyns) + 1023u) & ~1023u;
    const uint32_t AH = sbase;             // V hi    [128 e][32 kv] tf32
    const uint32_t AL = sbase + 16384;     // V lo
    const uint32_t BHt = sbase + 32768;    // phiK hi [128 d][32 kv]
    const uint32_t BLt = sbase + 49152;    // phiK lo
    uint32_t mbar = smem_u32(&s_mbar);

    if (wid == 0) {
        TCGEN05_ALLOC(smem_u32(&s_tmem), 128);
        TCGEN05_RELINQ();
    }
    if (tid == 0) MBARRIER_INIT(mbar, 1);
    if (tid < D) sZ[tid] = 0.f;
    __syncthreads();
    const uint32_t tmem = s_tmem;

    const int lane_c = tid & 127;          // column: e for V, d for K
    const int g = tid >> 7;                // row half: rows g*16 .. g*16+15
    float zacc = 0.f;

    const uint64_t adesc = MAKE_DESC(AH), aldesc = MAKE_DESC(AL);
    const uint64_t bdesc = MAKE_DESC(BHt), bldesc = MAKE_DESC(BLt);

    float aV[16], aK[16], bV[16], bK[16];  // ping-pong prefetch buffers

    {
        const size_t rb = (size_t)(g * 16) * D + lane_c;
        PREFETCH16(aV, Vp + rb);
        PREFETCH16(aK, Kp + rb);
        PREFETCH16(bV, Vp + (size_t)TK * D + rb);
        PREFETCH16(bK, Kp + (size_t)TK * D + rb);
    }

    for (int c2 = 0; c2 < NCHUNK; c2 += 2) {
        // ---- chunk c2 (buffer A) ----
        if (c2 > 0) mbar_wait(mbar, (uint32_t)((c2 - 1) & 1));
        kv_consume(aV, aK, zacc, lane_c, g, AH, AL, BHt, BLt);
        __syncthreads();
        FENCE_ASYNC_SHARED();
        if (wid == 0 && elect_one()) {
#pragma unroll
            for (int ks = 0; ks < 4; ks++) {
                uint64_t o = (uint64_t)(ks * 2);
                mma_tf32_ss(tmem, adesc + o, bdesc + o, IDESC_N128, !(c2 == 0 && ks == 0));
                mma_tf32_ss(tmem, adesc + o, bldesc + o, IDESC_N128, true);
                mma_tf32_ss(tmem, aldesc + o, bdesc + o, IDESC_N128, true);
            }
            TCGEN05_COMMIT(mbar);
        }
        if (c2 + 2 < NCHUNK) {
            const size_t rb = (size_t)((c2 + 2) * TK + g * 16) * D + lane_c;
            PREFETCH16(aV, Vp + rb);
            PREFETCH16(aK, Kp + rb);
        }

        // ---- chunk c2+1 (buffer B) ----
        mbar_wait(mbar, (uint32_t)(c2 & 1));
        kv_consume(bV, bK, zacc, lane_c, g, AH, AL, BHt, BLt);
        __syncthreads();
        FENCE_ASYNC_SHARED();
        if (wid == 0 && elect_one()) {
#pragma unroll
            for (int ks = 0; ks < 4; ks++) {
                uint64_t o = (uint64_t)(ks * 2);
                mma_tf32_ss(tmem, adesc + o, bdesc + o, IDESC_N128, true);
                mma_tf32_ss(tmem, adesc + o, bldesc + o, IDESC_N128, true);
                mma_tf32_ss(tmem, aldesc + o, bdesc + o, IDESC_N128, true);
            }
            TCGEN05_COMMIT(mbar);
        }
        if (c2 + 3 < NCHUNK) {
            const size_t rb = (size_t)((c2 + 3) * TK + g * 16) * D + lane_c;
            PREFETCH16(bV, Vp + rb);
            PREFETCH16(bK, Kp + rb);
        }
    }

    atomicAdd(&sZ[lane_c], zacc);
    mbar_wait(mbar, (uint32_t)((NCHUNK - 1) & 1));
    TCGEN05_FENCE_AFTER();

    {   // epilogue: plain stores to this split's partial buffer
        const int sub = wid & 3;
        const int colbase = (wid >> 2) * 64;
        const int row = sub * 32 + (tid & 31);       // e
        float* dst = g_part + ((size_t)split * BH + bh) * D * D + (size_t)row * D;
#pragma unroll
        for (int cb = 0; cb < 64; cb += 32) {
            uint32_t r[32];
            LDTM_X32(r, tmem + colbase + cb);
            TCGEN05_WAIT_LD();
#pragma unroll
            for (int j4 = 0; j4 < 8; j4++) {
                float4 o;
                o.x = __uint_as_float(r[j4*4+0]);
                o.y = __uint_as_float(r[j4*4+1]);
                o.z = __uint_as_float(r[j4*4+2]);
                o.w = __uint_as_float(r[j4*4+3]);
                *(float4*)(dst + colbase + cb + j4*4) = o;
            }
        }
    }
    __syncthreads();
    if (tid < D)
        g_Zpart[(size_t)split * BH * D + (size_t)bh * D + tid] = sZ[tid];

    if (tid == 0) MBARRIER_INVAL(mbar);
    __syncthreads();
    if (wid == 0) TCGEN05_DEALLOC(tmem, 128);

#else  // ------------------- FFMA fallback -------------------
    const int FKT = 16;
    float* As = (float*)dyns;                 // [FKT][D] phiK
    float* Bs = As + FKT * D;                 // [FKT][D] V

    const int tx = tid & 15;                  // e group
    const int ty = tid >> 4;                  // d group

    float acc[8][8];
#pragma unroll
    for (int i = 0; i < 8; i++)
#pragma unroll
        for (int j = 0; j < 8; j++) acc[i][j] = 0.f;
    float zacc = 0.f;

    for (int k0 = 0; k0 < KVCHUNK; k0 += FKT) {
#pragma unroll
        for (int r = 0; r < 2; r++) {
            int idx = tid + r * 256;
            int row = idx >> 5;
            int c4 = (idx & 31) * 4;
            float4 kq = *(const float4*)(Kp + (size_t)(k0 + row) * D + c4);
            As[row * D + c4 + 0] = phi(kq.x);
            As[row * D + c4 + 1] = phi(kq.y);
            As[row * D + c4 + 2] = phi(kq.z);
            As[row * D + c4 + 3] = phi(kq.w);
            float4 vq = *(const float4*)(Vp + (size_t)(k0 + row) * D + c4);
            Bs[row * D + c4 + 0] = vq.x;
            Bs[row * D + c4 + 1] = vq.y;
            Bs[row * D + c4 + 2] = vq.z;
            Bs[row * D + c4 + 3] = vq.w;
        }
        __syncthreads();
#pragma unroll
        for (int kk = 0; kk < FKT; kk++) {
            float a[8], b[8];
#pragma unroll
            for (int i = 0; i < 8; i++) a[i] = As[kk * D + ty + 16 * i];
#pragma unroll
            for (int j = 0; j < 8; j++) b[j] = Bs[kk * D + tx + 16 * j];
#pragma unroll
            for (int i = 0; i < 8; i++)
#pragma unroll
                for (int j = 0; j < 8; j++) acc[i][j] = fmaf(a[i], b[j], acc[i][j]);
        }
        if (tid < D) {
            float s = 0.f;
#pragma unroll
            for (int kk = 0; kk < FKT; kk++) s += As[kk * D + tid];
            zacc += s;
        }
        __syncthreads();
    }

    float* dst = g_part + ((size_t)split * BH + bh) * D * D;
#pragma unroll
    for (int i = 0; i < 8; i++) {
        int drow = ty + 16 * i;
#pragma unroll
        for (int j = 0; j < 8; j++) {
            int ecol = tx + 16 * j;
            dst[(size_t)ecol * D + drow] = acc[i][j];   // transposed store
        }
    }
    if (tid < D)
        g_Zpart[(size_t)split * BH * D + (size_t)bh * D + tid] = zacc;
#endif
}

// ---------------------------------------------------------------------------
// reduce_kernel: sum SPL partials -> KVT hi/lo (tf32-masked) + Z
// ---------------------------------------------------------------------------
__global__ __launch_bounds__(256) void reduce_kernel() {
    const int gid = blockIdx.x * blockDim.x + threadIdx.x;
    const int n4 = BH * D * D / 4;
    const size_t stride4 = (size_t)BH * D * D / 4;
    const float4* P = (const float4*)g_part;
    float4* Hi = (float4*)g_KVThi;
    float4* Lo = (float4*)g_KVTlo;

    for (int i = gid; i < n4; i += gridDim.x * blockDim.x) {
        float4 s = P[i];
#pragma unroll
        for (int sp = 1; sp < SPL; sp++) {
            float4 p = P[(size_t)sp * stride4 + i];
            s.x += p.x; s.y += p.y; s.z += p.z; s.w += p.w;
        }
        float4 h, l;
        split_tf32(s.x, h.x, l.x);
        split_tf32(s.y, h.y, l.y);
        split_tf32(s.z, h.z, l.z);
        split_tf32(s.w, h.w, l.w);
        Hi[i] = h; Lo[i] = l;
    }

    const int nz = BH * D;
    for (int i = gid; i < nz; i += gridDim.x * blockDim.x) {
        float s = 0.f;
#pragma unroll
        for (int sp = 0; sp < SPL; sp++) s += g_Zpart[(size_t)sp * nz + i];
        g_Z[i] = s;
    }
}

// ---------------------------------------------------------------------------
// out_kernel: D2[e][q] = sum_d KVT[e][d]*phiQ[q][d]; out[q][e] = D2 / (denom[q])
// A = KVT (M=128 e), B = phiQ (N=256 q). Direct coalesced STG epilogue.
// ---------------------------------------------------------------------------
__global__ __launch_bounds__(256, 2) void out_kernel(const float* __restrict__ Q,
                                                     float* __restrict__ out) {
    extern __shared__ char dyns[];
    __shared__ float Zs[D];
    __shared__ float sdenom[QT2];

    const int tid = threadIdx.x;
    const int bh = blockIdx.y;
    const int q0 = blockIdx.x * QT2;
    const float* Qp = Q + ((size_t)bh * QLEN + q0) * D;
    const float* KHp = g_KVThi + (size_t)bh * D * D;
    const float* KLp = g_KVTlo + (size_t)bh * D * D;

    if (tid < D) Zs[tid] = g_Z[bh * D + tid];
    sdenom[tid] = 0.f;

#if HAS_TCGEN05
    __shared__ uint32_t s_tmem;
    __shared__ __align__(8) unsigned long long s_mbar;
    const int wid = tid >> 5;
    const int lane = tid & 31;

    uint32_t sbase = (smem_u32(dyns) + 1023u) & ~1023u;
    const uint32_t KVH = sbase;             // KVT hi  [128 e][32 d]  16KB
    const uint32_t KVL = sbase + 16384;     // KVT lo
    const uint32_t QH  = sbase + 32768;     // phiQ hi [256 q][32 d]  32KB
    const uint32_t QL  = sbase + 65536;     // phiQ lo
    uint32_t mbar = smem_u32(&s_mbar);

    if (wid == 0) {
        TCGEN05_ALLOC(smem_u32(&s_tmem), 256);
        TCGEN05_RELINQ();
    }
    if (tid == 0) MBARRIER_INIT(mbar, 1);
    __syncthreads();
    const uint32_t tmem = s_tmem;

    const uint64_t ka = MAKE_DESC(KVH), kl = MAKE_DESC(KVL);
    const uint64_t qa = MAKE_DESC(QH),  ql = MAKE_DESC(QL);

    const int prow = tid >> 3;              // 0..31; rows prow + 32*s
    const int pc4 = (tid & 7) * 4;          // column within the 32-d chunk

    float qv[32];                           // prefetched Q (8 rows x 4 floats)

    // prologue: volatile prefetch of d-chunk 0 (8 q rows per thread)
#pragma unroll
    for (int s = 0; s < 8; s++)
        LDGV4(qv + s * 4, Qp + (size_t)(prow + 32 * s) * D + pc4);

    for (int it = 0; it < NDCH; it++) {
        if (it > 0) mbar_wait(mbar, (uint32_t)((it - 1) & 1));

        const int d0 = it * DK;
        // consume prefetched Q: phi + denominator + split + STS (256 q rows)
#pragma unroll
        for (int s = 0; s < 8; s++) {
            int row = prow + 32 * s;
            float p0 = phi(qv[s*4+0]), p1 = phi(qv[s*4+1]);
            float p2 = phi(qv[s*4+2]), p3 = phi(qv[s*4+3]);
            float dpart = p0 * Zs[d0 + pc4] + p1 * Zs[d0 + pc4 + 1]
                        + p2 * Zs[d0 + pc4 + 2] + p3 * Zs[d0 + pc4 + 3];
            dpart += __shfl_xor_sync(0xFFFFFFFFu, dpart, 4);
            dpart += __shfl_xor_sync(0xFFFFFFFFu, dpart, 2);
            dpart += __shfl_xor_sync(0xFFFFFFFFu, dpart, 1);
            if ((lane & 7) == 0) atomicAdd(&sdenom[row], dpart);
            float h0, l0, h1, l1, h2, l2, h3, l3;
            split_tf32(p0, h0, l0); split_tf32(p1, h1, l1);
            split_tf32(p2, h2, l2); split_tf32(p3, h3, l3);
            uint32_t off = koff(row, pc4);
            STS128(QH + off, __float_as_uint(h0), __float_as_uint(h1),
                             __float_as_uint(h2), __float_as_uint(h3));
            STS128(QL + off, __float_as_uint(l0), __float_as_uint(l1),
                             __float_as_uint(l2), __float_as_uint(l3));
        }
        // KVT tiles (128 e rows): pre-masked, pure copy (L2-resident)
#pragma unroll
        for (int s = 0; s < 4; s++) {
            int row = prow + 32 * s;
            uint32_t off = koff(row, pc4);
            float4 h = *(const float4*)(KHp + (size_t)row * D + d0 + pc4);
            STS128(KVH + off, __float_as_uint(h.x), __float_as_uint(h.y),
                              __float_as_uint(h.z), __float_as_uint(h.w));
            float4 l = *(const float4*)(KLp + (size_t)row * D + d0 + pc4);
            STS128(KVL + off, __float_as_uint(l.x), __float_as_uint(l.y),
                              __float_as_uint(l.z), __float_as_uint(l.w));
        }
        __syncthreads();
        FENCE_ASYNC_SHARED();

        if (wid == 0 && elect_one()) {
#pragma unroll
            for (int ks = 0; ks < 4; ks++) {
                uint64_t o = (uint64_t)(ks * 2);
                mma_tf32_ss(tmem, ka + o, qa + o, IDESC_N256, !(it == 0 && ks == 0));
                mma_tf32_ss(tmem, ka + o, ql + o, IDESC_N256, true);
                mma_tf32_ss(tmem, kl + o, qa + o, IDESC_N256, true);
            }
            TCGEN05_COMMIT(mbar);
        }

        // volatile prefetch of next d-chunk — flies during the MMA wait
        if (it + 1 < NDCH) {
            const int dn = (it + 1) * DK;
#pragma unroll
            for (int s = 0; s < 8; s++)
                LDGV4(qv + s * 4, Qp + (size_t)(prow + 32 * s) * D + dn + pc4);
        }
    }

    mbar_wait(mbar, (uint32_t)((NDCH - 1) & 1));
    TCGEN05_FENCE_AFTER();
    __syncthreads();

    // reciprocal denominators in-place
    {
        float dsum = sdenom[tid];
        __syncthreads();
        sdenom[tid] = 1.f / (dsum + EPS);
    }
    __syncthreads();

    // epilogue: TMEM lanes = e, cols = q -> coalesced STG.32 directly
    {
        const int sub = wid & 3;
        const int colbase = (wid >> 2) * 128;    // q half per warp group
        const int e = sub * 32 + lane;
        float* op = out + ((size_t)bh * QLEN + q0) * D + e;
#pragma unroll
        for (int cb = 0; cb < 128; cb += 32) {
            uint32_t r[32];
            LDTM_X32(r, tmem + colbase + cb);
            TCGEN05_WAIT_LD();
#pragma unroll
            for (int j = 0; j < 32; j++) {
                int qq = colbase + cb + j;
                op[(size_t)qq * D] = __uint_as_float(r[j]) * sdenom[qq];
            }
        }
    }

    __syncthreads();
    if (tid == 0) MBARRIER_INVAL(mbar);
    __syncthreads();
    if (wid == 0) TCGEN05_DEALLOC(tmem, 256);

#else  // ------------------- FFMA fallback -------------------
    const int FKT = 16;
    float* Qs = (float*)dyns;                 // [128][17] phiQ chunk
    float* Ks = Qs + 128 * 17;                // [128][17] KVT chunk

    const int tx = tid & 15;                  // e group
    const int ty = tid >> 4;                  // q group

    for (int half = 0; half < 2; half++) {
        const float* Qph = Qp + (size_t)half * 128 * D;
        float* outp = out + ((size_t)bh * QLEN + q0 + half * 128) * D;

        float acc[8][8];
#pragma unroll
        for (int i = 0; i < 8; i++)
#pragma unroll
            for (int j = 0; j < 8; j++) acc[i][j] = 0.f;
        float dsum = 0.f;
        __syncthreads();

        for (int k0 = 0; k0 < D; k0 += FKT) {
#pragma unroll
            for (int r = 0; r < 2; r++) {
                int idx = tid + r * 256;
                int row = idx >> 2;
                int c4 = (idx & 3) * 4;
                float4 qv2 = *(const float4*)(Qph + (size_t)row * D + k0 + c4);
                Qs[row * 17 + c4 + 0] = phi(qv2.x);
                Qs[row * 17 + c4 + 1] = phi(qv2.y);
                Qs[row * 17 + c4 + 2] = phi(qv2.z);
                Qs[row * 17 + c4 + 3] = phi(qv2.w);
                float4 kh = *(const float4*)(KHp + (size_t)row * D + k0 + c4);
                float4 klv = *(const float4*)(KLp + (size_t)row * D + k0 + c4);
                Ks[row * 17 + c4 + 0] = kh.x + klv.x;
                Ks[row * 17 + c4 + 1] = kh.y + klv.y;
                Ks[row * 17 + c4 + 2] = kh.z + klv.z;
                Ks[row * 17 + c4 + 3] = kh.w + klv.w;
            }
            __syncthreads();
#pragma unroll
            for (int kk = 0; kk < FKT; kk++) {
                float a[8], b[8];
#pragma unroll
                for (int i = 0; i < 8; i++) a[i] = Qs[(ty + 16 * i) * 17 + kk];
#pragma unroll
                for (int j = 0; j < 8; j++) b[j] = Ks[(tx + 16 * j) * 17 + kk];
#pragma unroll
                for (int i = 0; i < 8; i++)
#pragma unroll
                    for (int j = 0; j < 8; j++) acc[i][j] = fmaf(a[i], b[j], acc[i][j]);
            }
            if (tid < 128) {
                float s = 0.f;
#pragma unroll
                for (int kk = 0; kk < FKT; kk++) s += Qs[tid * 17 + kk] * Zs[k0 + kk];
                dsum += s;
            }
            __syncthreads();
        }

        if (tid < 128) sdenom[tid] = 1.f / (dsum + EPS);
        __syncthreads();

#pragma unroll
        for (int i = 0; i < 8; i++) {
            int row = ty + 16 * i;
            float rd = sdenom[row];
#pragma unroll
            for (int j = 0; j < 8; j++)
                outp[(size_t)row * D + tx + 16 * j] = acc[i][j] * rd;
        }
        __syncthreads();
    }
#endif
}

extern "C" void kernel_launch(void* const* d_in, const int* in_sizes, int n_in,
                              void* d_out, int out_size) {
    const float* Q = (const float*)d_in[0];
    const float* K = (const float*)d_in[1];
    const float* V = (const float*)d_in[2];
    float* out = (float*)d_out;

    cudaFuncSetAttribute(kv_kernel, cudaFuncAttributeMaxDynamicSharedMemorySize, 66560);
    cudaFuncSetAttribute(out_kernel, cudaFuncAttributeMaxDynamicSharedMemorySize, 99328);

    kv_kernel<<<BH * SPL, 256, 66560>>>(K, V);
    reduce_kernel<<<512, 256>>>();
    out_kernel<<<dim3(QLEN / QT2, BH), 256, 99328>>>(Q, out);
}